// round 2
// baseline (speedup 1.0000x reference)
#include <cuda_runtime.h>
#include <math.h>

#define BB 4
#define SS 4096
#define DD 512

// Scratch for Q, K, V (relu(x@W^T + b)), fp32. Allocation-free rule -> __device__ globals.
__device__ float g_Q[BB * SS * DD];
__device__ float g_K[BB * SS * DD];
__device__ float g_V[BB * SS * DD];

// ---------------------------------------------------------------------------
// Kernel 1: fused QKV projection.  Y[m,n] = relu( sum_k X[m,k] * W[n,k] + b[n] )
// M = B*S = 16384, N = 512, K = 512.  Classic 128x128x8 SIMT SGEMM, 8x8 microtile.
// blockIdx.z selects (Wq,bq,g_Q) / (Wk,bk,g_K) / (Wv,bv,g_V).
// ---------------------------------------------------------------------------
__global__ __launch_bounds__(256, 2) void qkv_proj_kernel(
    const float* __restrict__ X,
    const float* __restrict__ Wq, const float* __restrict__ bq,
    const float* __restrict__ Wk, const float* __restrict__ bk,
    const float* __restrict__ Wv, const float* __restrict__ bv)
{
    const int pz = blockIdx.z;
    const float* __restrict__ W    = (pz == 0) ? Wq : (pz == 1) ? Wk : Wv;
    const float* __restrict__ bias = (pz == 0) ? bq : (pz == 1) ? bk : bv;
    float* __restrict__ Y          = (pz == 0) ? g_Q : (pz == 1) ? g_K : g_V;

    __shared__ __align__(16) float As[8][132];  // +4 pad: conflict-free STS
    __shared__ __align__(16) float Bs[8][132];

    const int tid  = threadIdx.x;
    const int row0 = blockIdx.y * 128;   // M block
    const int col0 = blockIdx.x * 128;   // N block
    const int tx   = tid & 15;           // 16 col-tiles
    const int ty   = tid >> 4;           // 16 row-tiles

    float acc[8][8];
#pragma unroll
    for (int i = 0; i < 8; i++)
#pragma unroll
        for (int j = 0; j < 8; j++) acc[i][j] = 0.0f;

    const int lrow = tid >> 1;        // 0..127
    const int lk4  = (tid & 1) * 4;   // 0 or 4

    for (int k0 = 0; k0 < DD; k0 += 8) {
        // prefetch into regs
        float4 xa = *(const float4*)(X + (size_t)(row0 + lrow) * DD + k0 + lk4);
        float4 wb = *(const float4*)(W + (size_t)(col0 + lrow) * DD + k0 + lk4);
        __syncthreads();  // protect previous tile's reads
        As[lk4 + 0][lrow] = xa.x; As[lk4 + 1][lrow] = xa.y;
        As[lk4 + 2][lrow] = xa.z; As[lk4 + 3][lrow] = xa.w;
        Bs[lk4 + 0][lrow] = wb.x; Bs[lk4 + 1][lrow] = wb.y;
        Bs[lk4 + 2][lrow] = wb.z; Bs[lk4 + 3][lrow] = wb.w;
        __syncthreads();
#pragma unroll
        for (int kk = 0; kk < 8; kk++) {
            float a[8], b[8];
            *(float4*)(a + 0) = *(const float4*)&As[kk][ty * 8 + 0];
            *(float4*)(a + 4) = *(const float4*)&As[kk][ty * 8 + 4];
            *(float4*)(b + 0) = *(const float4*)&Bs[kk][tx * 8 + 0];
            *(float4*)(b + 4) = *(const float4*)&Bs[kk][tx * 8 + 4];
#pragma unroll
            for (int i = 0; i < 8; i++)
#pragma unroll
                for (int j = 0; j < 8; j++) acc[i][j] += a[i] * b[j];
        }
    }

    // epilogue: bias + relu, vectorized stores
    float bj[8];
#pragma unroll
    for (int j = 0; j < 8; j++) bj[j] = bias[col0 + tx * 8 + j];

#pragma unroll
    for (int i = 0; i < 8; i++) {
        const int r = row0 + ty * 8 + i;
        float* yrow = Y + (size_t)r * DD + col0 + tx * 8;
        float4 o0, o1;
        float v;
        v = acc[i][0] + bj[0]; o0.x = v > 0.f ? v : 0.f;
        v = acc[i][1] + bj[1]; o0.y = v > 0.f ? v : 0.f;
        v = acc[i][2] + bj[2]; o0.z = v > 0.f ? v : 0.f;
        v = acc[i][3] + bj[3]; o0.w = v > 0.f ? v : 0.f;
        v = acc[i][4] + bj[4]; o1.x = v > 0.f ? v : 0.f;
        v = acc[i][5] + bj[5]; o1.y = v > 0.f ? v : 0.f;
        v = acc[i][6] + bj[6]; o1.z = v > 0.f ? v : 0.f;
        v = acc[i][7] + bj[7]; o1.w = v > 0.f ? v : 0.f;
        *(float4*)(yrow + 0) = o0;
        *(float4*)(yrow + 4) = o1;
    }
}

// ---------------------------------------------------------------------------
// Kernel 2: flash attention, fp32.
// Grid: (S/32, B).  CTA = 256 threads = 8 warps; warp owns 4 q-rows.
// Per lane: q dims {lane*4 + 128*j + c}, j=0..3, c=0..3 (register-resident, pre-scaled).
// K/V tiles (32 rows x 512) double in dynamic smem (128 KB), streamed per tile.
// Per key: 16-FMA/lane dot -> 5-step butterfly -> warp-uniform online softmax.
// ---------------------------------------------------------------------------
__device__ __forceinline__ float dot4(float4 a, float4 b) {
    return a.x * b.x + a.y * b.y + a.z * b.z + a.w * b.w;
}

__global__ __launch_bounds__(256, 1) void attn_kernel(float* __restrict__ Out)
{
    extern __shared__ __align__(16) float sm[];
    float* Ks = sm;            // [32][512]
    float* Vs = sm + 32 * DD;  // [32][512]

    const int tid   = threadIdx.x;
    const int lane  = tid & 31;
    const int warp  = tid >> 5;
    const int b     = blockIdx.y;
    const int qbase = blockIdx.x * 32 + warp * 4;
    const int lane4 = lane * 4;

    const float scale = 0.044194173824159216f;  // 1/sqrt(512)

    // load + pre-scale q fragments
    float4 q[4][4];
#pragma unroll
    for (int r = 0; r < 4; r++) {
        const float* qp = g_Q + ((size_t)b * SS + qbase + r) * DD + lane4;
#pragma unroll
        for (int j = 0; j < 4; j++) {
            float4 t = *(const float4*)(qp + j * 128);
            t.x *= scale; t.y *= scale; t.z *= scale; t.w *= scale;
            q[r][j] = t;
        }
    }

    float4 acc[4][4];
#pragma unroll
    for (int r = 0; r < 4; r++)
#pragma unroll
        for (int j = 0; j < 4; j++) acc[r][j] = make_float4(0.f, 0.f, 0.f, 0.f);

    float mrow[4], lrow[4];
#pragma unroll
    for (int r = 0; r < 4; r++) { mrow[r] = -INFINITY; lrow[r] = 0.0f; }

    const float* Kg = g_K + (size_t)b * SS * DD;
    const float* Vg = g_V + (size_t)b * SS * DD;

    for (int kt = 0; kt < SS; kt += 32) {
        __syncthreads();  // previous tile fully consumed
        const float4* ksrc = (const float4*)(Kg + (size_t)kt * DD);
        const float4* vsrc = (const float4*)(Vg + (size_t)kt * DD);
        float4* kdst = (float4*)Ks;
        float4* vdst = (float4*)Vs;
#pragma unroll 4
        for (int i = tid; i < 32 * DD / 4; i += 256) {
            kdst[i] = ksrc[i];
            vdst[i] = vsrc[i];
        }
        __syncthreads();

#pragma unroll 2
        for (int kk = 0; kk < 32; kk++) {
            const float* kr = Ks + kk * DD + lane4;
            float4 k0 = *(const float4*)(kr + 0);
            float4 k1 = *(const float4*)(kr + 128);
            float4 k2 = *(const float4*)(kr + 256);
            float4 k3 = *(const float4*)(kr + 384);

            float s[4];
#pragma unroll
            for (int r = 0; r < 4; r++)
                s[r] = dot4(q[r][0], k0) + dot4(q[r][1], k1) +
                       dot4(q[r][2], k2) + dot4(q[r][3], k3);

#pragma unroll
            for (int off = 16; off > 0; off >>= 1) {
#pragma unroll
                for (int r = 0; r < 4; r++)
                    s[r] += __shfl_xor_sync(0xFFFFFFFFu, s[r], off);
            }
            // s[r] now warp-uniform

            const float* vr = Vs + kk * DD + lane4;
            float4 v0 = *(const float4*)(vr + 0);
            float4 v1 = *(const float4*)(vr + 128);
            float4 v2 = *(const float4*)(vr + 256);
            float4 v3 = *(const float4*)(vr + 384);

#pragma unroll
            for (int r = 0; r < 4; r++) {
                if (s[r] > mrow[r]) {  // warp-uniform, rare (~ln S times total)
                    float c = __expf(mrow[r] - s[r]);  // exp(-inf)=0 on first hit
                    lrow[r] *= c;
#pragma unroll
                    for (int j = 0; j < 4; j++) {
                        acc[r][j].x *= c; acc[r][j].y *= c;
                        acc[r][j].z *= c; acc[r][j].w *= c;
                    }
                    mrow[r] = s[r];
                }
                float pe = __expf(s[r] - mrow[r]);
                lrow[r] += pe;
                acc[r][0].x += pe * v0.x; acc[r][0].y += pe * v0.y;
                acc[r][0].z += pe * v0.z; acc[r][0].w += pe * v0.w;
                acc[r][1].x += pe * v1.x; acc[r][1].y += pe * v1.y;
                acc[r][1].z += pe * v1.z; acc[r][1].w += pe * v1.w;
                acc[r][2].x += pe * v2.x; acc[r][2].y += pe * v2.y;
                acc[r][2].z += pe * v2.z; acc[r][2].w += pe * v2.w;
                acc[r][3].x += pe * v3.x; acc[r][3].y += pe * v3.y;
                acc[r][3].z += pe * v3.z; acc[r][3].w += pe * v3.w;
            }
        }
    }

    // epilogue: normalize + store (coalesced float4)
#pragma unroll
    for (int r = 0; r < 4; r++) {
        const float inv = 1.0f / lrow[r];
        float* op = Out + ((size_t)b * SS + qbase + r) * DD + lane4;
#pragma unroll
        for (int j = 0; j < 4; j++) {
            float4 o = acc[r][j];
            o.x *= inv; o.y *= inv; o.z *= inv; o.w *= inv;
            *(float4*)(op + j * 128) = o;
        }
    }
}

// ---------------------------------------------------------------------------
extern "C" void kernel_launch(void* const* d_in, const int* in_sizes, int n_in,
                              void* d_out, int out_size)
{
    const float* X  = (const float*)d_in[0];
    const float* Wq = (const float*)d_in[1];
    const float* bq = (const float*)d_in[2];
    const float* Wk = (const float*)d_in[3];
    const float* bk = (const float*)d_in[4];
    const float* Wv = (const float*)d_in[5];
    const float* bv = (const float*)d_in[6];
    float* Out = (float*)d_out;

    const int attn_smem = 2 * 32 * DD * (int)sizeof(float);  // 128 KB
    cudaFuncSetAttribute(attn_kernel, cudaFuncAttributeMaxDynamicSharedMemorySize,
                         attn_smem);

    dim3 gp(DD / 128, (BB * SS) / 128, 3);
    qkv_proj_kernel<<<gp, 256>>>(X, Wq, bq, Wk, bk, Wv, bv);

    dim3 ga(SS / 32, BB);
    attn_kernel<<<ga, 256, attn_smem>>>(Out);
}

// round 4
// speedup vs baseline: 1.0004x; 1.0004x over previous
#include <cuda_runtime.h>
#include <math.h>

#define BB 4
#define SS 4096
#define DD 512

// Scratch for Q, K, V (relu(x@W^T + b)), fp32. Allocation-free rule -> __device__ globals.
__device__ float g_Q[BB * SS * DD];
__device__ float g_K[BB * SS * DD];
__device__ float g_V[BB * SS * DD];

// ---------------------------------------------------------------------------
// Kernel 1: fused QKV projection.  Y[m,n] = relu( sum_k X[m,k] * W[n,k] + b[n] )
// M = B*S = 16384, N = 512, K = 512.  Classic 128x128x8 SIMT SGEMM, 8x8 microtile.
// blockIdx.z selects (Wq,bq,g_Q) / (Wk,bk,g_K) / (Wv,bv,g_V).
// ---------------------------------------------------------------------------
__global__ __launch_bounds__(256, 2) void qkv_proj_kernel(
    const float* __restrict__ X,
    const float* __restrict__ Wq, const float* __restrict__ bq,
    const float* __restrict__ Wk, const float* __restrict__ bk,
    const float* __restrict__ Wv, const float* __restrict__ bv)
{
    const int pz = blockIdx.z;
    const float* __restrict__ W    = (pz == 0) ? Wq : (pz == 1) ? Wk : Wv;
    const float* __restrict__ bias = (pz == 0) ? bq : (pz == 1) ? bk : bv;
    float* __restrict__ Y          = (pz == 0) ? g_Q : (pz == 1) ? g_K : g_V;

    __shared__ __align__(16) float As[8][132];  // +4 pad: conflict-free STS
    __shared__ __align__(16) float Bs[8][132];

    const int tid  = threadIdx.x;
    const int row0 = blockIdx.y * 128;   // M block
    const int col0 = blockIdx.x * 128;   // N block
    const int tx   = tid & 15;           // 16 col-tiles
    const int ty   = tid >> 4;           // 16 row-tiles

    float acc[8][8];
#pragma unroll
    for (int i = 0; i < 8; i++)
#pragma unroll
        for (int j = 0; j < 8; j++) acc[i][j] = 0.0f;

    const int lrow = tid >> 1;        // 0..127
    const int lk4  = (tid & 1) * 4;   // 0 or 4

    for (int k0 = 0; k0 < DD; k0 += 8) {
        // prefetch into regs
        float4 xa = *(const float4*)(X + (size_t)(row0 + lrow) * DD + k0 + lk4);
        float4 wb = *(const float4*)(W + (size_t)(col0 + lrow) * DD + k0 + lk4);
        __syncthreads();  // protect previous tile's reads
        As[lk4 + 0][lrow] = xa.x; As[lk4 + 1][lrow] = xa.y;
        As[lk4 + 2][lrow] = xa.z; As[lk4 + 3][lrow] = xa.w;
        Bs[lk4 + 0][lrow] = wb.x; Bs[lk4 + 1][lrow] = wb.y;
        Bs[lk4 + 2][lrow] = wb.z; Bs[lk4 + 3][lrow] = wb.w;
        __syncthreads();
#pragma unroll
        for (int kk = 0; kk < 8; kk++) {
            float a[8], b[8];
            *(float4*)(a + 0) = *(const float4*)&As[kk][ty * 8 + 0];
            *(float4*)(a + 4) = *(const float4*)&As[kk][ty * 8 + 4];
            *(float4*)(b + 0) = *(const float4*)&Bs[kk][tx * 8 + 0];
            *(float4*)(b + 4) = *(const float4*)&Bs[kk][tx * 8 + 4];
#pragma unroll
            for (int i = 0; i < 8; i++)
#pragma unroll
                for (int j = 0; j < 8; j++) acc[i][j] += a[i] * b[j];
        }
    }

    // epilogue: bias + relu, vectorized stores
    float bj[8];
#pragma unroll
    for (int j = 0; j < 8; j++) bj[j] = bias[col0 + tx * 8 + j];

#pragma unroll
    for (int i = 0; i < 8; i++) {
        const int r = row0 + ty * 8 + i;
        float* yrow = Y + (size_t)r * DD + col0 + tx * 8;
        float4 o0, o1;
        float v;
        v = acc[i][0] + bj[0]; o0.x = v > 0.f ? v : 0.f;
        v = acc[i][1] + bj[1]; o0.y = v > 0.f ? v : 0.f;
        v = acc[i][2] + bj[2]; o0.z = v > 0.f ? v : 0.f;
        v = acc[i][3] + bj[3]; o0.w = v > 0.f ? v : 0.f;
        v = acc[i][4] + bj[4]; o1.x = v > 0.f ? v : 0.f;
        v = acc[i][5] + bj[5]; o1.y = v > 0.f ? v : 0.f;
        v = acc[i][6] + bj[6]; o1.z = v > 0.f ? v : 0.f;
        v = acc[i][7] + bj[7]; o1.w = v > 0.f ? v : 0.f;
        *(float4*)(yrow + 0) = o0;
        *(float4*)(yrow + 4) = o1;
    }
}

// ---------------------------------------------------------------------------
// Kernel 2: flash attention, fp32.
// Grid: (S/32, B).  CTA = 256 threads = 8 warps; warp owns 4 q-rows.
// Per lane: q dims {lane*4 + 128*j + c}, j=0..3, c=0..3 (register-resident, pre-scaled).
// K/V tiles (32 rows x 512) double in dynamic smem (128 KB), streamed per tile.
// Per key: 16-FMA/lane dot -> 5-step butterfly -> warp-uniform online softmax.
// ---------------------------------------------------------------------------
__device__ __forceinline__ float dot4(float4 a, float4 b) {
    return a.x * b.x + a.y * b.y + a.z * b.z + a.w * b.w;
}

__global__ __launch_bounds__(256, 1) void attn_kernel(float* __restrict__ Out)
{
    extern __shared__ __align__(16) float sm[];
    float* Ks = sm;            // [32][512]
    float* Vs = sm + 32 * DD;  // [32][512]

    const int tid   = threadIdx.x;
    const int lane  = tid & 31;
    const int warp  = tid >> 5;
    const int b     = blockIdx.y;
    const int qbase = blockIdx.x * 32 + warp * 4;
    const int lane4 = lane * 4;

    const float scale = 0.044194173824159216f;  // 1/sqrt(512)

    // load + pre-scale q fragments
    float4 q[4][4];
#pragma unroll
    for (int r = 0; r < 4; r++) {
        const float* qp = g_Q + ((size_t)b * SS + qbase + r) * DD + lane4;
#pragma unroll
        for (int j = 0; j < 4; j++) {
            float4 t = *(const float4*)(qp + j * 128);
            t.x *= scale; t.y *= scale; t.z *= scale; t.w *= scale;
            q[r][j] = t;
        }
    }

    float4 acc[4][4];
#pragma unroll
    for (int r = 0; r < 4; r++)
#pragma unroll
        for (int j = 0; j < 4; j++) acc[r][j] = make_float4(0.f, 0.f, 0.f, 0.f);

    float mrow[4], lrow[4];
#pragma unroll
    for (int r = 0; r < 4; r++) { mrow[r] = -INFINITY; lrow[r] = 0.0f; }

    const float* Kg = g_K + (size_t)b * SS * DD;
    const float* Vg = g_V + (size_t)b * SS * DD;

    for (int kt = 0; kt < SS; kt += 32) {
        __syncthreads();  // previous tile fully consumed
        const float4* ksrc = (const float4*)(Kg + (size_t)kt * DD);
        const float4* vsrc = (const float4*)(Vg + (size_t)kt * DD);
        float4* kdst = (float4*)Ks;
        float4* vdst = (float4*)Vs;
#pragma unroll 4
        for (int i = tid; i < 32 * DD / 4; i += 256) {
            kdst[i] = ksrc[i];
            vdst[i] = vsrc[i];
        }
        __syncthreads();

#pragma unroll 2
        for (int kk = 0; kk < 32; kk++) {
            const float* kr = Ks + kk * DD + lane4;
            float4 k0 = *(const float4*)(kr + 0);
            float4 k1 = *(const float4*)(kr + 128);
            float4 k2 = *(const float4*)(kr + 256);
            float4 k3 = *(const float4*)(kr + 384);

            float s[4];
#pragma unroll
            for (int r = 0; r < 4; r++)
                s[r] = dot4(q[r][0], k0) + dot4(q[r][1], k1) +
                       dot4(q[r][2], k2) + dot4(q[r][3], k3);

#pragma unroll
            for (int off = 16; off > 0; off >>= 1) {
#pragma unroll
                for (int r = 0; r < 4; r++)
                    s[r] += __shfl_xor_sync(0xFFFFFFFFu, s[r], off);
            }
            // s[r] now warp-uniform

            const float* vr = Vs + kk * DD + lane4;
            float4 v0 = *(const float4*)(vr + 0);
            float4 v1 = *(const float4*)(vr + 128);
            float4 v2 = *(const float4*)(vr + 256);
            float4 v3 = *(const float4*)(vr + 384);

#pragma unroll
            for (int r = 0; r < 4; r++) {
                if (s[r] > mrow[r]) {  // warp-uniform, rare (~ln S times total)
                    float c = __expf(mrow[r] - s[r]);  // exp(-inf)=0 on first hit
                    lrow[r] *= c;
#pragma unroll
                    for (int j = 0; j < 4; j++) {
                        acc[r][j].x *= c; acc[r][j].y *= c;
                        acc[r][j].z *= c; acc[r][j].w *= c;
                    }
                    mrow[r] = s[r];
                }
                float pe = __expf(s[r] - mrow[r]);
                lrow[r] += pe;
                acc[r][0].x += pe * v0.x; acc[r][0].y += pe * v0.y;
                acc[r][0].z += pe * v0.z; acc[r][0].w += pe * v0.w;
                acc[r][1].x += pe * v1.x; acc[r][1].y += pe * v1.y;
                acc[r][1].z += pe * v1.z; acc[r][1].w += pe * v1.w;
                acc[r][2].x += pe * v2.x; acc[r][2].y += pe * v2.y;
                acc[r][2].z += pe * v2.z; acc[r][2].w += pe * v2.w;
                acc[r][3].x += pe * v3.x; acc[r][3].y += pe * v3.y;
                acc[r][3].z += pe * v3.z; acc[r][3].w += pe * v3.w;
            }
        }
    }

    // epilogue: normalize + store (coalesced float4)
#pragma unroll
    for (int r = 0; r < 4; r++) {
        const float inv = 1.0f / lrow[r];
        float* op = Out + ((size_t)b * SS + qbase + r) * DD + lane4;
#pragma unroll
        for (int j = 0; j < 4; j++) {
            float4 o = acc[r][j];
            o.x *= inv; o.y *= inv; o.z *= inv; o.w *= inv;
            *(float4*)(op + j * 128) = o;
        }
    }
}

// ---------------------------------------------------------------------------
extern "C" void kernel_launch(void* const* d_in, const int* in_sizes, int n_in,
                              void* d_out, int out_size)
{
    const float* X  = (const float*)d_in[0];
    const float* Wq = (const float*)d_in[1];
    const float* bq = (const float*)d_in[2];
    const float* Wk = (const float*)d_in[3];
    const float* bk = (const float*)d_in[4];
    const float* Wv = (const float*)d_in[5];
    const float* bv = (const float*)d_in[6];
    float* Out = (float*)d_out;

    const int attn_smem = 2 * 32 * DD * (int)sizeof(float);  // 128 KB
    cudaFuncSetAttribute(attn_kernel, cudaFuncAttributeMaxDynamicSharedMemorySize,
                         attn_smem);

    dim3 gp(DD / 128, (BB * SS) / 128, 3);
    qkv_proj_kernel<<<gp, 256>>>(X, Wq, bq, Wk, bk, Wv, bv);

    dim3 ga(SS / 32, BB);
    attn_kernel<<<ga, 256, attn_smem>>>(Out);
}

// round 11
// speedup vs baseline: 3.7999x; 3.7986x over previous
#include <cuda_runtime.h>
#include <cstdint>
#include <math.h>

#define BB 4
#define SS 4096
#define DD 512

__device__ float g_Q[BB * SS * DD];
__device__ float g_K[BB * SS * DD];
__device__ float g_V[BB * SS * DD];

__device__ __forceinline__ float tf32r(float x) {
    float y; asm("cvt.rna.tf32.f32 %0, %1;" : "=f"(y) : "f"(x)); return y;
}
__device__ __forceinline__ float ex2(float x) {
    float y; asm("ex2.approx.ftz.f32 %0, %1;" : "=f"(y) : "f"(x)); return y;
}
__device__ __forceinline__ void mma8(float* d, uint32_t a0, uint32_t a1,
                                     uint32_t a2, uint32_t a3,
                                     uint32_t b0, uint32_t b1) {
    asm volatile(
        "mma.sync.aligned.m16n8k8.row.col.f32.tf32.tf32.f32 "
        "{%0,%1,%2,%3}, {%4,%5,%6,%7}, {%8,%9}, {%0,%1,%2,%3};"
        : "+f"(d[0]), "+f"(d[1]), "+f"(d[2]), "+f"(d[3])
        : "r"(a0), "r"(a1), "r"(a2), "r"(a3), "r"(b0), "r"(b1));
}

// ---------------------------------------------------------------------------
// Kernel 1: fused QKV projection (fp32 SIMT), outputs tf32-rounded.
// ---------------------------------------------------------------------------
__global__ __launch_bounds__(256, 2) void qkv_proj_kernel(
    const float* __restrict__ X,
    const float* __restrict__ Wq, const float* __restrict__ bq,
    const float* __restrict__ Wk, const float* __restrict__ bk,
    const float* __restrict__ Wv, const float* __restrict__ bv)
{
    const int pz = blockIdx.z;
    const float* __restrict__ W    = (pz == 0) ? Wq : (pz == 1) ? Wk : Wv;
    const float* __restrict__ bias = (pz == 0) ? bq : (pz == 1) ? bk : bv;
    float* __restrict__ Y          = (pz == 0) ? g_Q : (pz == 1) ? g_K : g_V;

    __shared__ __align__(16) float As[8][132];
    __shared__ __align__(16) float Bs[8][132];

    const int tid  = threadIdx.x;
    const int row0 = blockIdx.y * 128;
    const int col0 = blockIdx.x * 128;
    const int tx   = tid & 15;
    const int ty   = tid >> 4;

    float acc[8][8];
#pragma unroll
    for (int i = 0; i < 8; i++)
#pragma unroll
        for (int j = 0; j < 8; j++) acc[i][j] = 0.0f;

    const int lrow = tid >> 1;
    const int lk4  = (tid & 1) * 4;

    for (int k0 = 0; k0 < DD; k0 += 8) {
        float4 xa = *(const float4*)(X + (size_t)(row0 + lrow) * DD + k0 + lk4);
        float4 wb = *(const float4*)(W + (size_t)(col0 + lrow) * DD + k0 + lk4);
        __syncthreads();
        As[lk4 + 0][lrow] = xa.x; As[lk4 + 1][lrow] = xa.y;
        As[lk4 + 2][lrow] = xa.z; As[lk4 + 3][lrow] = xa.w;
        Bs[lk4 + 0][lrow] = wb.x; Bs[lk4 + 1][lrow] = wb.y;
        Bs[lk4 + 2][lrow] = wb.z; Bs[lk4 + 3][lrow] = wb.w;
        __syncthreads();
#pragma unroll
        for (int kk = 0; kk < 8; kk++) {
            float a[8], b[8];
            *(float4*)(a + 0) = *(const float4*)&As[kk][ty * 8 + 0];
            *(float4*)(a + 4) = *(const float4*)&As[kk][ty * 8 + 4];
            *(float4*)(b + 0) = *(const float4*)&Bs[kk][tx * 8 + 0];
            *(float4*)(b + 4) = *(const float4*)&Bs[kk][tx * 8 + 4];
#pragma unroll
            for (int i = 0; i < 8; i++)
#pragma unroll
                for (int j = 0; j < 8; j++) acc[i][j] += a[i] * b[j];
        }
    }

    float bj[8];
#pragma unroll
    for (int j = 0; j < 8; j++) bj[j] = bias[col0 + tx * 8 + j];

#pragma unroll
    for (int i = 0; i < 8; i++) {
        const int r = row0 + ty * 8 + i;
        float* yrow = Y + (size_t)r * DD + col0 + tx * 8;
        float4 o0, o1;
        float v;
        v = acc[i][0] + bj[0]; o0.x = tf32r(v > 0.f ? v : 0.f);
        v = acc[i][1] + bj[1]; o0.y = tf32r(v > 0.f ? v : 0.f);
        v = acc[i][2] + bj[2]; o0.z = tf32r(v > 0.f ? v : 0.f);
        v = acc[i][3] + bj[3]; o0.w = tf32r(v > 0.f ? v : 0.f);
        v = acc[i][4] + bj[4]; o1.x = tf32r(v > 0.f ? v : 0.f);
        v = acc[i][5] + bj[5]; o1.y = tf32r(v > 0.f ? v : 0.f);
        v = acc[i][6] + bj[6]; o1.z = tf32r(v > 0.f ? v : 0.f);
        v = acc[i][7] + bj[7]; o1.w = tf32r(v > 0.f ? v : 0.f);
        *(float4*)(yrow + 0) = o0;
        *(float4*)(yrow + 4) = o1;
    }
}

// ---------------------------------------------------------------------------
// Kernel 2: mma.sync tf32 flash attention.
// Grid (64, 4); CTA 256 thr = warps (mg 0..3, hf 0..1). Q-tile 64 rows resident.
// GEMM1: warp computes S[16 x 32 keys] (hf splits keys), K in 4 chunks of 128 dims.
// Softmax: p = exp(s/sqrt(512)) (no shift needed: relu'd q,k => s in [0,~10]).
// GEMM2: warp computes O[16 x 256 dims] (hf splits dims), V in 4 chunks.
// O accumulates in registers across all 64 key tiles; normalize at end.
// ---------------------------------------------------------------------------
#define QSTR 520
#define KSTR 132
#define VSTR 136
#define PSTR 68
#define KVS  (64 * QSTR)            /* 33280 */
#define PSO  (KVS + 64 * VSTR)      /* 41984 */
#define LSO  (PSO + 64 * PSTR)      /* 46336 */
#define ATTN_SMEM ((LSO + 128) * 4) /* 185856 B */

__global__ __launch_bounds__(256, 1) void attn_mma_kernel(float* __restrict__ Out)
{
    extern __shared__ __align__(16) float sm[];
    const int tid = threadIdx.x, lane = tid & 31, warp = tid >> 5;
    const int mg = warp & 3, hf = warp >> 2;
    const int g = lane >> 2, t = lane & 3;
    const int qt = blockIdx.x, b = blockIdx.y;

    const float* Qg = g_Q + ((size_t)b * SS + qt * 64) * DD;
    const float* Kb = g_K + (size_t)b * SS * DD;
    const float* Vb = g_V + (size_t)b * SS * DD;

    // Q resident: 64 x 512, stride 520 (==8 mod 32: conflict-free A-frags)
    for (int i = tid; i < 64 * 128; i += 256) {
        int r = i >> 7, c4 = i & 127;
        *(float4*)&sm[r * QSTR + c4 * 4] = *(const float4*)&Qg[(size_t)r * DD + c4 * 4];
    }

    float oacc[2][16][4];
#pragma unroll
    for (int oc = 0; oc < 2; oc++)
#pragma unroll
        for (int nb = 0; nb < 16; nb++)
#pragma unroll
            for (int j = 0; j < 4; j++) oacc[oc][nb][j] = 0.f;

    float lsum0 = 0.f, lsum1 = 0.f;
    const float C1 = 0.06375871651397899f;  // log2(e)/sqrt(512)
    const int rowA = 16 * mg + g;

    for (int kt = 0; kt < 64; kt++) {
        const float* Kt = Kb + (size_t)(kt * 64) * DD;
        const float* Vt = Vb + (size_t)(kt * 64) * DD;

        float sacc[4][4];
#pragma unroll
        for (int nb = 0; nb < 4; nb++)
#pragma unroll
            for (int j = 0; j < 4; j++) sacc[nb][j] = 0.f;

        // ---- GEMM1: S = Q . K^T over 4 dim-chunks of 128 ----
        for (int c = 0; c < 4; c++) {
            __syncthreads();  // KV buffer free (prev chunk / prev tile consumed)
            for (int i = tid; i < 64 * 32; i += 256) {
                int r = i >> 5, c4 = i & 31;
                *(float4*)&sm[KVS + r * KSTR + c4 * 4] =
                    *(const float4*)&Kt[(size_t)r * DD + c * 128 + c4 * 4];
            }
            __syncthreads();
            const float* qp = &sm[rowA * QSTR + c * 128];
            const float* kp = &sm[KVS + (hf * 32 + g) * KSTR];
#pragma unroll
            for (int ks = 0; ks < 16; ks++) {
                uint32_t a0 = __float_as_uint(qp[ks * 8 + t]);
                uint32_t a1 = __float_as_uint(qp[8 * QSTR + ks * 8 + t]);
                uint32_t a2 = __float_as_uint(qp[ks * 8 + t + 4]);
                uint32_t a3 = __float_as_uint(qp[8 * QSTR + ks * 8 + t + 4]);
#pragma unroll
                for (int nb = 0; nb < 4; nb++) {
                    uint32_t b0 = __float_as_uint(kp[nb * 8 * KSTR + ks * 8 + t]);
                    uint32_t b1 = __float_as_uint(kp[nb * 8 * KSTR + ks * 8 + t + 4]);
                    mma8(sacc[nb], a0, a1, a2, a3, b0, b1);
                }
            }
        }

        // ---- softmax: p = exp2(s*C1), accumulate row sums, P -> smem ----
        float* pr = &sm[PSO + rowA * PSTR + hf * 32 + 2 * t];
#pragma unroll
        for (int nb = 0; nb < 4; nb++) {
            float p0 = ex2(sacc[nb][0] * C1), p1 = ex2(sacc[nb][1] * C1);
            float p2 = ex2(sacc[nb][2] * C1), p3 = ex2(sacc[nb][3] * C1);
            lsum0 += p0 + p1; lsum1 += p2 + p3;
            *(float2*)&pr[nb * 8] = make_float2(tf32r(p0), tf32r(p1));
            *(float2*)&pr[8 * PSTR + nb * 8] = make_float2(tf32r(p2), tf32r(p3));
        }

        // ---- GEMM2: O += P . V over 4 dim-chunks of 128 ----
        for (int vc = 0; vc < 4; vc++) {
            __syncthreads();  // P complete everywhere; K reads done -> reuse buffer
            for (int i = tid; i < 64 * 32; i += 256) {
                int r = i >> 5, c4 = i & 31;
                *(float4*)&sm[KVS + r * VSTR + c4 * 4] =
                    *(const float4*)&Vt[(size_t)r * DD + vc * 128 + c4 * 4];
            }
            __syncthreads();
            if ((vc >> 1) == hf) {
                const int oc = vc & 1;
                const float* pp = &sm[PSO + rowA * PSTR];
#pragma unroll
                for (int ks = 0; ks < 8; ks++) {
                    uint32_t a0 = __float_as_uint(pp[ks * 8 + t]);
                    uint32_t a1 = __float_as_uint(pp[8 * PSTR + ks * 8 + t]);
                    uint32_t a2 = __float_as_uint(pp[ks * 8 + t + 4]);
                    uint32_t a3 = __float_as_uint(pp[8 * PSTR + ks * 8 + t + 4]);
                    const float* vp = &sm[KVS + (ks * 8 + t) * VSTR + g];
#pragma unroll
                    for (int nb = 0; nb < 16; nb++) {
                        uint32_t b0 = __float_as_uint(vp[nb * 8]);
                        uint32_t b1 = __float_as_uint(vp[4 * VSTR + nb * 8]);
                        mma8(oacc[oc][nb], a0, a1, a2, a3, b0, b1);
                    }
                }
            }
        }
    }

    // ---- row-sum reduce (over t lanes, then over hf warps via smem) ----
    lsum0 += __shfl_xor_sync(~0u, lsum0, 1); lsum0 += __shfl_xor_sync(~0u, lsum0, 2);
    lsum1 += __shfl_xor_sync(~0u, lsum1, 1); lsum1 += __shfl_xor_sync(~0u, lsum1, 2);
    if (t == 0) {
        sm[LSO + rowA * 2 + hf] = lsum0;
        sm[LSO + (rowA + 8) * 2 + hf] = lsum1;
    }
    __syncthreads();
    const float inv0 = 1.f / (sm[LSO + rowA * 2] + sm[LSO + rowA * 2 + 1]);
    const float inv1 = 1.f / (sm[LSO + (rowA + 8) * 2] + sm[LSO + (rowA + 8) * 2 + 1]);

    float* Og = Out + ((size_t)b * SS + qt * 64) * DD;
#pragma unroll
    for (int oc = 0; oc < 2; oc++)
#pragma unroll
        for (int nb = 0; nb < 16; nb++) {
            int dcol = hf * 256 + oc * 128 + nb * 8 + 2 * t;
            *(float2*)&Og[(size_t)rowA * DD + dcol] =
                make_float2(oacc[oc][nb][0] * inv0, oacc[oc][nb][1] * inv0);
            *(float2*)&Og[(size_t)(rowA + 8) * DD + dcol] =
                make_float2(oacc[oc][nb][2] * inv1, oacc[oc][nb][3] * inv1);
        }
}

// ---------------------------------------------------------------------------
extern "C" void kernel_launch(void* const* d_in, const int* in_sizes, int n_in,
                              void* d_out, int out_size)
{
    const float* X  = (const float*)d_in[0];
    const float* Wq = (const float*)d_in[1];
    const float* bq = (const float*)d_in[2];
    const float* Wk = (const float*)d_in[3];
    const float* bk = (const float*)d_in[4];
    const float* Wv = (const float*)d_in[5];
    const float* bv = (const float*)d_in[6];
    float* Out = (float*)d_out;

    cudaFuncSetAttribute(attn_mma_kernel,
                         cudaFuncAttributeMaxDynamicSharedMemorySize, ATTN_SMEM);

    dim3 gp(DD / 128, (BB * SS) / 128, 3);
    qkv_proj_kernel<<<gp, 256>>>(X, Wq, bq, Wk, bk, Wv, bv);

    dim3 ga(SS / 64, BB);
    attn_mma_kernel<<<ga, 256, ATTN_SMEM>>>(Out);
}

// round 12
// speedup vs baseline: 6.2035x; 1.6325x over previous
#include <cuda_runtime.h>
#include <cstdint>
#include <math.h>

#define BB 4
#define SS 4096
#define DD 512

__device__ float g_Q[BB * SS * DD];
__device__ float g_K[BB * SS * DD];
__device__ float g_V[BB * SS * DD];

__device__ __forceinline__ float tf32r(float x) {
    float y; asm("cvt.rna.tf32.f32 %0, %1;" : "=f"(y) : "f"(x)); return y;
}
__device__ __forceinline__ float ex2(float x) {
    float y; asm("ex2.approx.ftz.f32 %0, %1;" : "=f"(y) : "f"(x)); return y;
}
__device__ __forceinline__ void mma8(float* d, uint32_t a0, uint32_t a1,
                                     uint32_t a2, uint32_t a3,
                                     uint32_t b0, uint32_t b1) {
    asm volatile(
        "mma.sync.aligned.m16n8k8.row.col.f32.tf32.tf32.f32 "
        "{%0,%1,%2,%3}, {%4,%5,%6,%7}, {%8,%9}, {%0,%1,%2,%3};"
        : "+f"(d[0]), "+f"(d[1]), "+f"(d[2]), "+f"(d[3])
        : "r"(a0), "r"(a1), "r"(a2), "r"(a3), "r"(b0), "r"(b1));
}

// ===========================================================================
// Kernel 1: QKV projection via mma.sync tf32.
// Y = relu(X . W^T + b), per-CTA tile 128(M) x 128(N), K-chunks of 64,
// double-buffered smem + register prefetch. Warps: mg=warp&3 (32 rows),
// nh=warp>>2 (64 cols). Strides 68 (==4 mod 32 -> conflict-free frags).
// ===========================================================================
#define PJ_STR 68
#define PJ_SMEM (34816 * 4)   /* A0,B0,A1,B1: 4 x 128 x 68 floats */

__global__ __launch_bounds__(256, 1) void qkv_mma_kernel(
    const float* __restrict__ X,
    const float* __restrict__ Wq, const float* __restrict__ bq,
    const float* __restrict__ Wk, const float* __restrict__ bk,
    const float* __restrict__ Wv, const float* __restrict__ bv)
{
    extern __shared__ __align__(16) float sm[];
    const int pz = blockIdx.z;
    const float* __restrict__ W    = (pz == 0) ? Wq : (pz == 1) ? Wk : Wv;
    const float* __restrict__ bias = (pz == 0) ? bq : (pz == 1) ? bk : bv;
    float* __restrict__ Y          = (pz == 0) ? g_Q : (pz == 1) ? g_K : g_V;

    const int tid = threadIdx.x, lane = tid & 31, warp = tid >> 5;
    const int mg = warp & 3, nh = warp >> 2;
    const int g = lane >> 2, t = lane & 3;
    const int row0 = blockIdx.y * 128, col0 = blockIdx.x * 128;

    float4 pfx[8], pfw[8];
#pragma unroll
    for (int j = 0; j < 8; j++) {
        int i = tid + j * 256, r = i >> 4, c4 = i & 15;
        pfx[j] = __ldg((const float4*)&X[(size_t)(row0 + r) * DD + c4 * 4]);
        pfw[j] = __ldg((const float4*)&W[(size_t)(col0 + r) * DD + c4 * 4]);
    }

    float acc[2][8][4];
#pragma unroll
    for (int mt = 0; mt < 2; mt++)
#pragma unroll
        for (int nb = 0; nb < 8; nb++)
#pragma unroll
            for (int j = 0; j < 4; j++) acc[mt][nb][j] = 0.f;

    for (int c = 0; c < 8; c++) {
        float* Ab = sm + (c & 1) * 17408;
        float* Bb = Ab + 8704;
#pragma unroll
        for (int j = 0; j < 8; j++) {
            int i = tid + j * 256, r = i >> 4, c4 = i & 15;
            *(float4*)&Ab[r * PJ_STR + c4 * 4] = pfx[j];
            *(float4*)&Bb[r * PJ_STR + c4 * 4] = pfw[j];
        }
        if (c < 7) {
#pragma unroll
            for (int j = 0; j < 8; j++) {
                int i = tid + j * 256, r = i >> 4, c4 = i & 15;
                pfx[j] = __ldg((const float4*)&X[(size_t)(row0 + r) * DD + (c + 1) * 64 + c4 * 4]);
                pfw[j] = __ldg((const float4*)&W[(size_t)(col0 + r) * DD + (c + 1) * 64 + c4 * 4]);
            }
        }
        __syncthreads();
        const float* ap = &Ab[(32 * mg + g) * PJ_STR];
        const float* bp = &Bb[(64 * nh + g) * PJ_STR];
#pragma unroll
        for (int ks = 0; ks < 8; ks++) {
            uint32_t a00 = __float_as_uint(ap[ks * 8 + t]);
            uint32_t a01 = __float_as_uint(ap[8 * PJ_STR + ks * 8 + t]);
            uint32_t a02 = __float_as_uint(ap[ks * 8 + t + 4]);
            uint32_t a03 = __float_as_uint(ap[8 * PJ_STR + ks * 8 + t + 4]);
            uint32_t a10 = __float_as_uint(ap[16 * PJ_STR + ks * 8 + t]);
            uint32_t a11 = __float_as_uint(ap[24 * PJ_STR + ks * 8 + t]);
            uint32_t a12 = __float_as_uint(ap[16 * PJ_STR + ks * 8 + t + 4]);
            uint32_t a13 = __float_as_uint(ap[24 * PJ_STR + ks * 8 + t + 4]);
#pragma unroll
            for (int nb = 0; nb < 8; nb++) {
                uint32_t b0 = __float_as_uint(bp[nb * 8 * PJ_STR + ks * 8 + t]);
                uint32_t b1 = __float_as_uint(bp[nb * 8 * PJ_STR + ks * 8 + t + 4]);
                mma8(acc[0][nb], a00, a01, a02, a03, b0, b1);
                mma8(acc[1][nb], a10, a11, a12, a13, b0, b1);
            }
        }
    }

#pragma unroll
    for (int mt = 0; mt < 2; mt++)
#pragma unroll
        for (int nb = 0; nb < 8; nb++) {
            int col = col0 + 64 * nh + 8 * nb + 2 * t;
            float b0v = __ldg(&bias[col]), b1v = __ldg(&bias[col + 1]);
            int r0 = row0 + 32 * mg + 16 * mt + g, r1 = r0 + 8;
            float v; float2 o;
            v = acc[mt][nb][0] + b0v; o.x = tf32r(v > 0.f ? v : 0.f);
            v = acc[mt][nb][1] + b1v; o.y = tf32r(v > 0.f ? v : 0.f);
            *(float2*)&Y[(size_t)r0 * DD + col] = o;
            v = acc[mt][nb][2] + b0v; o.x = tf32r(v > 0.f ? v : 0.f);
            v = acc[mt][nb][3] + b1v; o.y = tf32r(v > 0.f ? v : 0.f);
            *(float2*)&Y[(size_t)r1 * DD + col] = o;
        }
}

// ===========================================================================
// Kernel 2: mma.sync tf32 flash attention, software-pipelined.
// Double-buffered KV chunk smem + register prefetch; one sync per phase.
// QSTR 516 (==4 mod 32, fixes R9's 2-way A-frag conflict).
// ===========================================================================
#define QSTR 516
#define KSTR 132
#define VSTR 136
#define PSTR 68
#define KV0  (64 * QSTR)           /* 33024 */
#define KVB  (64 * VSTR)           /* 8704 per buffer */
#define PSO  (KV0 + 2 * KVB)       /* 50432 */
#define LSO  (PSO + 64 * PSTR)     /* 54784 */
#define ATTN_SMEM ((LSO + 128) * 4) /* 219648 B */

__device__ __forceinline__ void pfetch64(float4* pf, const float* __restrict__ src,
                                         int tid) {
#pragma unroll
    for (int j = 0; j < 8; j++) {
        int i = tid + j * 256, r = i >> 5, c4 = i & 31;
        pf[j] = __ldg((const float4*)&src[(size_t)r * DD + c4 * 4]);
    }
}
__device__ __forceinline__ void sts64(const float4* pf, float* dst, int stride,
                                      int tid) {
#pragma unroll
    for (int j = 0; j < 8; j++) {
        int i = tid + j * 256, r = i >> 5, c4 = i & 31;
        *(float4*)&dst[r * stride + c4 * 4] = pf[j];
    }
}

__global__ __launch_bounds__(256, 1) void attn_mma_kernel(float* __restrict__ Out)
{
    extern __shared__ __align__(16) float sm[];
    const int tid = threadIdx.x, lane = tid & 31, warp = tid >> 5;
    const int mg = warp & 3, hf = warp >> 2;
    const int g = lane >> 2, t = lane & 3;
    const int qt = blockIdx.x, b = blockIdx.y;

    const float* Qg = g_Q + ((size_t)b * SS + qt * 64) * DD;
    const float* Kb = g_K + (size_t)b * SS * DD;
    const float* Vb = g_V + (size_t)b * SS * DD;

    // Q resident: 64 x 512, stride 516
    for (int i = tid; i < 64 * 128; i += 256) {
        int r = i >> 7, c4 = i & 127;
        *(float4*)&sm[r * QSTR + c4 * 4] = *(const float4*)&Qg[(size_t)r * DD + c4 * 4];
    }

    float4 pf[8];
    pfetch64(pf, Kb, tid);   // tile 0, chunk 0

    float oacc[2][16][4];
#pragma unroll
    for (int oc = 0; oc < 2; oc++)
#pragma unroll
        for (int nb = 0; nb < 16; nb++)
#pragma unroll
            for (int j = 0; j < 4; j++) oacc[oc][nb][j] = 0.f;

    float lsum0 = 0.f, lsum1 = 0.f;
    const float C1 = 0.06375871651397899f;  // log2(e)/sqrt(512)
    const int rowA = 16 * mg + g;
    int buf = 0;

    for (int kt = 0; kt < 64; kt++) {
        const float* Kt = Kb + (size_t)(kt * 64) * DD;
        const float* Vt = Vb + (size_t)(kt * 64) * DD;
        const float* Kn = Kb + (size_t)(((kt + 1) & 63) * 64) * DD;

        float sacc[4][4];
#pragma unroll
        for (int nb = 0; nb < 4; nb++)
#pragma unroll
            for (int j = 0; j < 4; j++) sacc[nb][j] = 0.f;

        // ---- GEMM1: S = Q . K^T, 4 dim-chunks of 128, pipelined ----
        for (int c = 0; c < 4; c++) {
            float* kbuf = &sm[KV0 + buf * KVB];
            sts64(pf, kbuf, KSTR, tid);
            if (c < 3) pfetch64(pf, Kt + (c + 1) * 128, tid);
            else       pfetch64(pf, Vt, tid);
            __syncthreads();
            const float* qp = &sm[rowA * QSTR + c * 128];
            const float* kp = &kbuf[(hf * 32 + g) * KSTR];
#pragma unroll
            for (int ks = 0; ks < 16; ks++) {
                uint32_t a0 = __float_as_uint(qp[ks * 8 + t]);
                uint32_t a1 = __float_as_uint(qp[8 * QSTR + ks * 8 + t]);
                uint32_t a2 = __float_as_uint(qp[ks * 8 + t + 4]);
                uint32_t a3 = __float_as_uint(qp[8 * QSTR + ks * 8 + t + 4]);
#pragma unroll
                for (int nb = 0; nb < 4; nb++) {
                    uint32_t b0 = __float_as_uint(kp[nb * 8 * KSTR + ks * 8 + t]);
                    uint32_t b1 = __float_as_uint(kp[nb * 8 * KSTR + ks * 8 + t + 4]);
                    mma8(sacc[nb], a0, a1, a2, a3, b0, b1);
                }
            }
            buf ^= 1;
        }

        // ---- softmax: p = exp2(s*C1) (relu'd q,k => s>=0 bounded) ----
        float* pr = &sm[PSO + rowA * PSTR + hf * 32 + 2 * t];
#pragma unroll
        for (int nb = 0; nb < 4; nb++) {
            float p0 = ex2(sacc[nb][0] * C1), p1 = ex2(sacc[nb][1] * C1);
            float p2 = ex2(sacc[nb][2] * C1), p3 = ex2(sacc[nb][3] * C1);
            lsum0 += p0 + p1; lsum1 += p2 + p3;
            *(float2*)&pr[nb * 8] = make_float2(tf32r(p0), tf32r(p1));
            *(float2*)&pr[8 * PSTR + nb * 8] = make_float2(tf32r(p2), tf32r(p3));
        }

        // ---- GEMM2: O += P . V, 4 dim-chunks, pipelined ----
        for (int vc = 0; vc < 4; vc++) {
            float* vbuf = &sm[KV0 + buf * KVB];
            sts64(pf, vbuf, VSTR, tid);
            if (vc < 3) pfetch64(pf, Vt + (vc + 1) * 128, tid);
            else        pfetch64(pf, Kn, tid);
            __syncthreads();
            if ((vc >> 1) == hf) {
                const int oc = vc & 1;
                const float* pp = &sm[PSO + rowA * PSTR];
#pragma unroll
                for (int ks = 0; ks < 8; ks++) {
                    uint32_t a0 = __float_as_uint(pp[ks * 8 + t]);
                    uint32_t a1 = __float_as_uint(pp[8 * PSTR + ks * 8 + t]);
                    uint32_t a2 = __float_as_uint(pp[ks * 8 + t + 4]);
                    uint32_t a3 = __float_as_uint(pp[8 * PSTR + ks * 8 + t + 4]);
                    const float* vp = &vbuf[(ks * 8 + t) * VSTR + g];
#pragma unroll
                    for (int nb = 0; nb < 16; nb++) {
                        uint32_t b0 = __float_as_uint(vp[nb * 8]);
                        uint32_t b1 = __float_as_uint(vp[4 * VSTR + nb * 8]);
                        mma8(oacc[oc][nb], a0, a1, a2, a3, b0, b1);
                    }
                }
            }
            buf ^= 1;
        }
    }

    // ---- row-sum reduce (t lanes, then hf warps via smem) ----
    lsum0 += __shfl_xor_sync(~0u, lsum0, 1); lsum0 += __shfl_xor_sync(~0u, lsum0, 2);
    lsum1 += __shfl_xor_sync(~0u, lsum1, 1); lsum1 += __shfl_xor_sync(~0u, lsum1, 2);
    if (t == 0) {
        sm[LSO + rowA * 2 + hf] = lsum0;
        sm[LSO + (rowA + 8) * 2 + hf] = lsum1;
    }
    __syncthreads();
    const float inv0 = 1.f / (sm[LSO + rowA * 2] + sm[LSO + rowA * 2 + 1]);
    const float inv1 = 1.f / (sm[LSO + (rowA + 8) * 2] + sm[LSO + (rowA + 8) * 2 + 1]);

    float* Og = Out + ((size_t)b * SS + qt * 64) * DD;
#pragma unroll
    for (int oc = 0; oc < 2; oc++)
#pragma unroll
        for (int nb = 0; nb < 16; nb++) {
            int dcol = hf * 256 + oc * 128 + nb * 8 + 2 * t;
            *(float2*)&Og[(size_t)rowA * DD + dcol] =
                make_float2(oacc[oc][nb][0] * inv0, oacc[oc][nb][1] * inv0);
            *(float2*)&Og[(size_t)(rowA + 8) * DD + dcol] =
                make_float2(oacc[oc][nb][2] * inv1, oacc[oc][nb][3] * inv1);
        }
}

// ===========================================================================
extern "C" void kernel_launch(void* const* d_in, const int* in_sizes, int n_in,
                              void* d_out, int out_size)
{
    const float* X  = (const float*)d_in[0];
    const float* Wq = (const float*)d_in[1];
    const float* bq = (const float*)d_in[2];
    const float* Wk = (const float*)d_in[3];
    const float* bk = (const float*)d_in[4];
    const float* Wv = (const float*)d_in[5];
    const float* bv = (const float*)d_in[6];
    float* Out = (float*)d_out;

    cudaFuncSetAttribute(qkv_mma_kernel,
                         cudaFuncAttributeMaxDynamicSharedMemorySize, PJ_SMEM);
    cudaFuncSetAttribute(attn_mma_kernel,
                         cudaFuncAttributeMaxDynamicSharedMemorySize, ATTN_SMEM);

    dim3 gp(DD / 128, (BB * SS) / 128, 3);
    qkv_mma_kernel<<<gp, 256, PJ_SMEM>>>(X, Wq, bq, Wk, bk, Wv, bv);

    dim3 ga(SS / 64, BB);
    attn_mma_kernel<<<ga, 256, ATTN_SMEM>>>(Out);
}

// round 13
// speedup vs baseline: 6.7877x; 1.0942x over previous
#include <cuda_runtime.h>
#include <cstdint>
#include <math.h>

#define BB 4
#define SS 4096
#define DD 512

__device__ float g_Q[BB * SS * DD];
__device__ float g_K[BB * SS * DD];
__device__ float g_V[BB * SS * DD];

__device__ __forceinline__ float tf32r(float x) {
    float y; asm("cvt.rna.tf32.f32 %0, %1;" : "=f"(y) : "f"(x)); return y;
}
__device__ __forceinline__ float4 tf32r4(float4 v) {
    v.x = tf32r(v.x); v.y = tf32r(v.y); v.z = tf32r(v.z); v.w = tf32r(v.w);
    return v;
}
__device__ __forceinline__ float ex2(float x) {
    float y; asm("ex2.approx.ftz.f32 %0, %1;" : "=f"(y) : "f"(x)); return y;
}
__device__ __forceinline__ void mma8(float* d, uint32_t a0, uint32_t a1,
                                     uint32_t a2, uint32_t a3,
                                     uint32_t b0, uint32_t b1) {
    asm volatile(
        "mma.sync.aligned.m16n8k8.row.col.f32.tf32.tf32.f32 "
        "{%0,%1,%2,%3}, {%4,%5,%6,%7}, {%8,%9}, {%0,%1,%2,%3};"
        : "+f"(d[0]), "+f"(d[1]), "+f"(d[2]), "+f"(d[3])
        : "r"(a0), "r"(a1), "r"(a2), "r"(a3), "r"(b0), "r"(b1));
}

// ===========================================================================
// Kernel 1: QKV projection via mma.sync tf32.
// X/W are rna-rounded to tf32 at the STS stage (unbiased: fixes the R12
// truncation bias that pushed rel_err to 7e-4).
// ===========================================================================
#define PJ_STR 68
#define PJ_SMEM (34816 * 4)

__global__ __launch_bounds__(256, 1) void qkv_mma_kernel(
    const float* __restrict__ X,
    const float* __restrict__ Wq, const float* __restrict__ bq,
    const float* __restrict__ Wk, const float* __restrict__ bk,
    const float* __restrict__ Wv, const float* __restrict__ bv)
{
    extern __shared__ __align__(16) float sm[];
    const int pz = blockIdx.z;
    const float* __restrict__ W    = (pz == 0) ? Wq : (pz == 1) ? Wk : Wv;
    const float* __restrict__ bias = (pz == 0) ? bq : (pz == 1) ? bk : bv;
    float* __restrict__ Y          = (pz == 0) ? g_Q : (pz == 1) ? g_K : g_V;

    const int tid = threadIdx.x, lane = tid & 31, warp = tid >> 5;
    const int mg = warp & 3, nh = warp >> 2;
    const int g = lane >> 2, t = lane & 3;
    const int row0 = blockIdx.y * 128, col0 = blockIdx.x * 128;

    float4 pfx[8], pfw[8];
#pragma unroll
    for (int j = 0; j < 8; j++) {
        int i = tid + j * 256, r = i >> 4, c4 = i & 15;
        pfx[j] = __ldg((const float4*)&X[(size_t)(row0 + r) * DD + c4 * 4]);
        pfw[j] = __ldg((const float4*)&W[(size_t)(col0 + r) * DD + c4 * 4]);
    }

    float acc[2][8][4];
#pragma unroll
    for (int mt = 0; mt < 2; mt++)
#pragma unroll
        for (int nb = 0; nb < 8; nb++)
#pragma unroll
            for (int j = 0; j < 4; j++) acc[mt][nb][j] = 0.f;

    for (int c = 0; c < 8; c++) {
        float* Ab = sm + (c & 1) * 17408;
        float* Bb = Ab + 8704;
#pragma unroll
        for (int j = 0; j < 8; j++) {
            int i = tid + j * 256, r = i >> 4, c4 = i & 15;
            *(float4*)&Ab[r * PJ_STR + c4 * 4] = tf32r4(pfx[j]);
            *(float4*)&Bb[r * PJ_STR + c4 * 4] = tf32r4(pfw[j]);
        }
        if (c < 7) {
#pragma unroll
            for (int j = 0; j < 8; j++) {
                int i = tid + j * 256, r = i >> 4, c4 = i & 15;
                pfx[j] = __ldg((const float4*)&X[(size_t)(row0 + r) * DD + (c + 1) * 64 + c4 * 4]);
                pfw[j] = __ldg((const float4*)&W[(size_t)(col0 + r) * DD + (c + 1) * 64 + c4 * 4]);
            }
        }
        __syncthreads();
        const float* ap = &Ab[(32 * mg + g) * PJ_STR];
        const float* bp = &Bb[(64 * nh + g) * PJ_STR];
#pragma unroll
        for (int ks = 0; ks < 8; ks++) {
            uint32_t a00 = __float_as_uint(ap[ks * 8 + t]);
            uint32_t a01 = __float_as_uint(ap[8 * PJ_STR + ks * 8 + t]);
            uint32_t a02 = __float_as_uint(ap[ks * 8 + t + 4]);
            uint32_t a03 = __float_as_uint(ap[8 * PJ_STR + ks * 8 + t + 4]);
            uint32_t a10 = __float_as_uint(ap[16 * PJ_STR + ks * 8 + t]);
            uint32_t a11 = __float_as_uint(ap[24 * PJ_STR + ks * 8 + t]);
            uint32_t a12 = __float_as_uint(ap[16 * PJ_STR + ks * 8 + t + 4]);
            uint32_t a13 = __float_as_uint(ap[24 * PJ_STR + ks * 8 + t + 4]);
#pragma unroll
            for (int nb = 0; nb < 8; nb++) {
                uint32_t b0 = __float_as_uint(bp[nb * 8 * PJ_STR + ks * 8 + t]);
                uint32_t b1 = __float_as_uint(bp[nb * 8 * PJ_STR + ks * 8 + t + 4]);
                mma8(acc[0][nb], a00, a01, a02, a03, b0, b1);
                mma8(acc[1][nb], a10, a11, a12, a13, b0, b1);
            }
        }
        __syncthreads();
    }

#pragma unroll
    for (int mt = 0; mt < 2; mt++)
#pragma unroll
        for (int nb = 0; nb < 8; nb++) {
            int col = col0 + 64 * nh + 8 * nb + 2 * t;
            float b0v = __ldg(&bias[col]), b1v = __ldg(&bias[col + 1]);
            int r0 = row0 + 32 * mg + 16 * mt + g, r1 = r0 + 8;
            float v; float2 o;
            v = acc[mt][nb][0] + b0v; o.x = tf32r(v > 0.f ? v : 0.f);
            v = acc[mt][nb][1] + b1v; o.y = tf32r(v > 0.f ? v : 0.f);
            *(float2*)&Y[(size_t)r0 * DD + col] = o;
            v = acc[mt][nb][2] + b0v; o.x = tf32r(v > 0.f ? v : 0.f);
            v = acc[mt][nb][3] + b1v; o.y = tf32r(v > 0.f ? v : 0.f);
            *(float2*)&Y[(size_t)r1 * DD + col] = o;
        }
}

// ===========================================================================
// Kernel 2: mma.sync tf32 flash attention, 512 threads / 16 warps.
// warp=(mg: 16 q-rows, hq: 0..3). GEMM1: hq splits 64 keys (S[16x16]/warp,
// accumulated over 4 dim-chunk phases). GEMM2: hq splits the 128-dim V chunk
// into 32-dim slices -> ALL warps active every phase. Double-buffered chunks
// + register prefetch, one sync per phase.
// ===========================================================================
#define QSTR 516
#define KSTR 132
#define VSTR 136
#define PSTR 68
#define KV0  (64 * QSTR)            /* 33024 */
#define KVB  (64 * VSTR)            /* 8704 per buffer */
#define PSO  (KV0 + 2 * KVB)        /* 50432 */
#define LSO  (PSO + 64 * PSTR)      /* 54784 */
#define ATTN_SMEM ((LSO + 256) * 4) /* 220160 B */

__device__ __forceinline__ void pfetch64w(float4* pf, const float* __restrict__ src,
                                          int tid) {
#pragma unroll
    for (int j = 0; j < 4; j++) {
        int i = tid + j * 512, r = i >> 5, c4 = i & 31;
        pf[j] = __ldg((const float4*)&src[(size_t)r * DD + c4 * 4]);
    }
}
__device__ __forceinline__ void sts64w(const float4* pf, float* dst, int stride,
                                       int tid) {
#pragma unroll
    for (int j = 0; j < 4; j++) {
        int i = tid + j * 512, r = i >> 5, c4 = i & 31;
        *(float4*)&dst[r * stride + c4 * 4] = pf[j];
    }
}

__global__ __launch_bounds__(512, 1) void attn_mma_kernel(float* __restrict__ Out)
{
    extern __shared__ __align__(16) float sm[];
    const int tid = threadIdx.x, lane = tid & 31, warp = tid >> 5;
    const int mg = warp & 3, hq = warp >> 2;   // hq: 0..3
    const int g = lane >> 2, t = lane & 3;
    const int qt = blockIdx.x, b = blockIdx.y;

    const float* Qg = g_Q + ((size_t)b * SS + qt * 64) * DD;
    const float* Kb = g_K + (size_t)b * SS * DD;
    const float* Vb = g_V + (size_t)b * SS * DD;

    // Q resident: 64 x 512, stride 516 (==4 mod 32)
    for (int i = tid; i < 64 * 128; i += 512) {
        int r = i >> 7, c4 = i & 127;
        *(float4*)&sm[r * QSTR + c4 * 4] = *(const float4*)&Qg[(size_t)r * DD + c4 * 4];
    }

    float4 pf[4];
    pfetch64w(pf, Kb, tid);   // tile 0, K chunk 0

    float oacc[4][4][4];      // [dim-chunk][nb][frag]
#pragma unroll
    for (int vc = 0; vc < 4; vc++)
#pragma unroll
        for (int nb = 0; nb < 4; nb++)
#pragma unroll
            for (int j = 0; j < 4; j++) oacc[vc][nb][j] = 0.f;

    float lsum0 = 0.f, lsum1 = 0.f;
    const float C1 = 0.06375871651397899f;  // log2(e)/sqrt(512)
    const int rowA = 16 * mg + g;
    int buf = 0;

    for (int kt = 0; kt < 64; kt++) {
        const float* Kt = Kb + (size_t)(kt * 64) * DD;
        const float* Vt = Vb + (size_t)(kt * 64) * DD;
        const float* Kn = Kb + (size_t)(((kt + 1) & 63) * 64) * DD;

        float sacc[2][4];
#pragma unroll
        for (int nb = 0; nb < 2; nb++)
#pragma unroll
            for (int j = 0; j < 4; j++) sacc[nb][j] = 0.f;

        // ---- GEMM1: S = Q . K^T, 4 dim-chunks of 128, pipelined ----
        for (int c = 0; c < 4; c++) {
            float* kbuf = &sm[KV0 + buf * KVB];
            sts64w(pf, kbuf, KSTR, tid);
            if (c < 3) pfetch64w(pf, Kt + (c + 1) * 128, tid);
            else       pfetch64w(pf, Vt, tid);
            __syncthreads();
            const float* qp = &sm[rowA * QSTR + c * 128];
            const float* kp = &kbuf[(hq * 16 + g) * KSTR];
#pragma unroll
            for (int ks = 0; ks < 16; ks++) {
                uint32_t a0 = __float_as_uint(qp[ks * 8 + t]);
                uint32_t a1 = __float_as_uint(qp[8 * QSTR + ks * 8 + t]);
                uint32_t a2 = __float_as_uint(qp[ks * 8 + t + 4]);
                uint32_t a3 = __float_as_uint(qp[8 * QSTR + ks * 8 + t + 4]);
#pragma unroll
                for (int nb = 0; nb < 2; nb++) {
                    uint32_t b0 = __float_as_uint(kp[nb * 8 * KSTR + ks * 8 + t]);
                    uint32_t b1 = __float_as_uint(kp[nb * 8 * KSTR + ks * 8 + t + 4]);
                    mma8(sacc[nb], a0, a1, a2, a3, b0, b1);
                }
            }
            buf ^= 1;
        }

        // ---- softmax: p = exp2(s*C1) (relu'd q,k => s>=0 bounded) ----
        float* pr = &sm[PSO + rowA * PSTR + hq * 16 + 2 * t];
#pragma unroll
        for (int nb = 0; nb < 2; nb++) {
            float p0 = ex2(sacc[nb][0] * C1), p1 = ex2(sacc[nb][1] * C1);
            float p2 = ex2(sacc[nb][2] * C1), p3 = ex2(sacc[nb][3] * C1);
            lsum0 += p0 + p1; lsum1 += p2 + p3;
            *(float2*)&pr[nb * 8] = make_float2(tf32r(p0), tf32r(p1));
            *(float2*)&pr[8 * PSTR + nb * 8] = make_float2(tf32r(p2), tf32r(p3));
        }

        // ---- GEMM2: O += P . V, 4 dim-chunks, all warps active ----
        for (int vc = 0; vc < 4; vc++) {
            float* vbuf = &sm[KV0 + buf * KVB];
            sts64w(pf, vbuf, VSTR, tid);
            if (vc < 3) pfetch64w(pf, Vt + (vc + 1) * 128, tid);
            else        pfetch64w(pf, Kn, tid);
            __syncthreads();
            const float* pp = &sm[PSO + rowA * PSTR];
#pragma unroll
            for (int ks = 0; ks < 8; ks++) {
                uint32_t a0 = __float_as_uint(pp[ks * 8 + t]);
                uint32_t a1 = __float_as_uint(pp[8 * PSTR + ks * 8 + t]);
                uint32_t a2 = __float_as_uint(pp[ks * 8 + t + 4]);
                uint32_t a3 = __float_as_uint(pp[8 * PSTR + ks * 8 + t + 4]);
                const float* vp = &vbuf[(ks * 8 + t) * VSTR + hq * 32 + g];
#pragma unroll
                for (int nb = 0; nb < 4; nb++) {
                    uint32_t b0 = __float_as_uint(vp[nb * 8]);
                    uint32_t b1 = __float_as_uint(vp[4 * VSTR + nb * 8]);
                    mma8(oacc[vc][nb], a0, a1, a2, a3, b0, b1);
                }
            }
            buf ^= 1;
        }
    }

    // ---- row-sum reduce: t lanes via shuffle, hq warps via smem ----
    lsum0 += __shfl_xor_sync(~0u, lsum0, 1); lsum0 += __shfl_xor_sync(~0u, lsum0, 2);
    lsum1 += __shfl_xor_sync(~0u, lsum1, 1); lsum1 += __shfl_xor_sync(~0u, lsum1, 2);
    if (t == 0) {
        sm[LSO + rowA * 4 + hq] = lsum0;
        sm[LSO + (rowA + 8) * 4 + hq] = lsum1;
    }
    __syncthreads();
    const float inv0 = 1.f / (sm[LSO + rowA * 4 + 0] + sm[LSO + rowA * 4 + 1] +
                              sm[LSO + rowA * 4 + 2] + sm[LSO + rowA * 4 + 3]);
    const float inv1 = 1.f / (sm[LSO + (rowA + 8) * 4 + 0] + sm[LSO + (rowA + 8) * 4 + 1] +
                              sm[LSO + (rowA + 8) * 4 + 2] + sm[LSO + (rowA + 8) * 4 + 3]);

    float* Og = Out + ((size_t)b * SS + qt * 64) * DD;
#pragma unroll
    for (int vc = 0; vc < 4; vc++)
#pragma unroll
        for (int nb = 0; nb < 4; nb++) {
            int dcol = vc * 128 + hq * 32 + nb * 8 + 2 * t;
            *(float2*)&Og[(size_t)rowA * DD + dcol] =
                make_float2(oacc[vc][nb][0] * inv0, oacc[vc][nb][1] * inv0);
            *(float2*)&Og[(size_t)(rowA + 8) * DD + dcol] =
                make_float2(oacc[vc][nb][2] * inv1, oacc[vc][nb][3] * inv1);
        }
}

// ===========================================================================
extern "C" void kernel_launch(void* const* d_in, const int* in_sizes, int n_in,
                              void* d_out, int out_size)
{
    const float* X  = (const float*)d_in[0];
    const float* Wq = (const float*)d_in[1];
    const float* bq = (const float*)d_in[2];
    const float* Wk = (const float*)d_in[3];
    const float* bk = (const float*)d_in[4];
    const float* Wv = (const float*)d_in[5];
    const float* bv = (const float*)d_in[6];
    float* Out = (float*)d_out;

    cudaFuncSetAttribute(qkv_mma_kernel,
                         cudaFuncAttributeMaxDynamicSharedMemorySize, PJ_SMEM);
    cudaFuncSetAttribute(attn_mma_kernel,
                         cudaFuncAttributeMaxDynamicSharedMemorySize, ATTN_SMEM);

    dim3 gp(DD / 128, (BB * SS) / 128, 3);
    qkv_mma_kernel<<<gp, 256, PJ_SMEM>>>(X, Wq, bq, Wk, bk, Wv, bv);

    dim3 ga(SS / 64, BB);
    attn_mma_kernel<<<ga, 512, ATTN_SMEM>>>(Out);
}

// round 14
// speedup vs baseline: 8.1576x; 1.2018x over previous
#include <cuda_runtime.h>
#include <cstdint>
#include <math.h>

#define BB 4
#define SS 4096
#define DD 512

__device__ float g_Q[BB * SS * DD];
__device__ float g_K[BB * SS * DD];
__device__ float g_V[BB * SS * DD];

__device__ __forceinline__ float tf32r(float x) {
    float y; asm("cvt.rna.tf32.f32 %0, %1;" : "=f"(y) : "f"(x)); return y;
}
__device__ __forceinline__ float4 tf32r4(float4 v) {
    v.x = tf32r(v.x); v.y = tf32r(v.y); v.z = tf32r(v.z); v.w = tf32r(v.w);
    return v;
}
__device__ __forceinline__ float ex2(float x) {
    float y; asm("ex2.approx.ftz.f32 %0, %1;" : "=f"(y) : "f"(x)); return y;
}
__device__ __forceinline__ void mma8(float* d, uint32_t a0, uint32_t a1,
                                     uint32_t a2, uint32_t a3,
                                     uint32_t b0, uint32_t b1) {
    asm volatile(
        "mma.sync.aligned.m16n8k8.row.col.f32.tf32.tf32.f32 "
        "{%0,%1,%2,%3}, {%4,%5,%6,%7}, {%8,%9}, {%0,%1,%2,%3};"
        : "+f"(d[0]), "+f"(d[1]), "+f"(d[2]), "+f"(d[3])
        : "r"(a0), "r"(a1), "r"(a2), "r"(a3), "r"(b0), "r"(b1));
}
__device__ __forceinline__ uint32_t smem_u32(const void* p) {
    return (uint32_t)__cvta_generic_to_shared(p);
}
#define CP_ASYNC16(dst_u32, src_ptr) \
    asm volatile("cp.async.cg.shared.global [%0], [%1], 16;" \
                 :: "r"(dst_u32), "l"(src_ptr))
#define CP_COMMIT() asm volatile("cp.async.commit_group;" ::: "memory")
#define CP_WAIT(N)  asm volatile("cp.async.wait_group %0;" :: "n"(N) : "memory")

// ===========================================================================
// Kernel 1: QKV projection via mma.sync tf32 (unchanged from R13; rna-rounded).
// ===========================================================================
#define PJ_STR 68
#define PJ_SMEM (34816 * 4)

__global__ __launch_bounds__(256, 1) void qkv_mma_kernel(
    const float* __restrict__ X,
    const float* __restrict__ Wq, const float* __restrict__ bq,
    const float* __restrict__ Wk, const float* __restrict__ bk,
    const float* __restrict__ Wv, const float* __restrict__ bv)
{
    extern __shared__ __align__(16) float sm[];
    const int pz = blockIdx.z;
    const float* __restrict__ W    = (pz == 0) ? Wq : (pz == 1) ? Wk : Wv;
    const float* __restrict__ bias = (pz == 0) ? bq : (pz == 1) ? bk : bv;
    float* __restrict__ Y          = (pz == 0) ? g_Q : (pz == 1) ? g_K : g_V;

    const int tid = threadIdx.x, lane = tid & 31, warp = tid >> 5;
    const int mg = warp & 3, nh = warp >> 2;
    const int g = lane >> 2, t = lane & 3;
    const int row0 = blockIdx.y * 128, col0 = blockIdx.x * 128;

    float4 pfx[8], pfw[8];
#pragma unroll
    for (int j = 0; j < 8; j++) {
        int i = tid + j * 256, r = i >> 4, c4 = i & 15;
        pfx[j] = __ldg((const float4*)&X[(size_t)(row0 + r) * DD + c4 * 4]);
        pfw[j] = __ldg((const float4*)&W[(size_t)(col0 + r) * DD + c4 * 4]);
    }

    float acc[2][8][4];
#pragma unroll
    for (int mt = 0; mt < 2; mt++)
#pragma unroll
        for (int nb = 0; nb < 8; nb++)
#pragma unroll
            for (int j = 0; j < 4; j++) acc[mt][nb][j] = 0.f;

    for (int c = 0; c < 8; c++) {
        float* Ab = sm + (c & 1) * 17408;
        float* Bb = Ab + 8704;
#pragma unroll
        for (int j = 0; j < 8; j++) {
            int i = tid + j * 256, r = i >> 4, c4 = i & 15;
            *(float4*)&Ab[r * PJ_STR + c4 * 4] = tf32r4(pfx[j]);
            *(float4*)&Bb[r * PJ_STR + c4 * 4] = tf32r4(pfw[j]);
        }
        if (c < 7) {
#pragma unroll
            for (int j = 0; j < 8; j++) {
                int i = tid + j * 256, r = i >> 4, c4 = i & 15;
                pfx[j] = __ldg((const float4*)&X[(size_t)(row0 + r) * DD + (c + 1) * 64 + c4 * 4]);
                pfw[j] = __ldg((const float4*)&W[(size_t)(col0 + r) * DD + (c + 1) * 64 + c4 * 4]);
            }
        }
        __syncthreads();
        const float* ap = &Ab[(32 * mg + g) * PJ_STR];
        const float* bp = &Bb[(64 * nh + g) * PJ_STR];
#pragma unroll
        for (int ks = 0; ks < 8; ks++) {
            uint32_t a00 = __float_as_uint(ap[ks * 8 + t]);
            uint32_t a01 = __float_as_uint(ap[8 * PJ_STR + ks * 8 + t]);
            uint32_t a02 = __float_as_uint(ap[ks * 8 + t + 4]);
            uint32_t a03 = __float_as_uint(ap[8 * PJ_STR + ks * 8 + t + 4]);
            uint32_t a10 = __float_as_uint(ap[16 * PJ_STR + ks * 8 + t]);
            uint32_t a11 = __float_as_uint(ap[24 * PJ_STR + ks * 8 + t]);
            uint32_t a12 = __float_as_uint(ap[16 * PJ_STR + ks * 8 + t + 4]);
            uint32_t a13 = __float_as_uint(ap[24 * PJ_STR + ks * 8 + t + 4]);
#pragma unroll
            for (int nb = 0; nb < 8; nb++) {
                uint32_t b0 = __float_as_uint(bp[nb * 8 * PJ_STR + ks * 8 + t]);
                uint32_t b1 = __float_as_uint(bp[nb * 8 * PJ_STR + ks * 8 + t + 4]);
                mma8(acc[0][nb], a00, a01, a02, a03, b0, b1);
                mma8(acc[1][nb], a10, a11, a12, a13, b0, b1);
            }
        }
        __syncthreads();
    }

#pragma unroll
    for (int mt = 0; mt < 2; mt++)
#pragma unroll
        for (int nb = 0; nb < 8; nb++) {
            int col = col0 + 64 * nh + 8 * nb + 2 * t;
            float b0v = __ldg(&bias[col]), b1v = __ldg(&bias[col + 1]);
            int r0 = row0 + 32 * mg + 16 * mt + g, r1 = r0 + 8;
            float v; float2 o;
            v = acc[mt][nb][0] + b0v; o.x = tf32r(v > 0.f ? v : 0.f);
            v = acc[mt][nb][1] + b1v; o.y = tf32r(v > 0.f ? v : 0.f);
            *(float2*)&Y[(size_t)r0 * DD + col] = o;
            v = acc[mt][nb][2] + b0v; o.x = tf32r(v > 0.f ? v : 0.f);
            v = acc[mt][nb][3] + b1v; o.y = tf32r(v > 0.f ? v : 0.f);
            *(float2*)&Y[(size_t)r1 * DD + col] = o;
        }
}

// ===========================================================================
// Kernel 2: mma.sync tf32 flash attention. 512 thr / 16 warps = (mg4, hq4).
// Key-tile 128. Q streamed (64-dim chunks, db). GEMM1: warp S[16x32], nb=4.
// GEMM2: V streamed in 16-key x 512-dim chunks (db), warp O[16x128], nb=16
// chains; P A-frags re-read only 4x (keyed phases) instead of 16x.
// All movement via cp.async; double-buffer choreography with wait_group.
// ===========================================================================
#define QSTR2  68
#define KSTR2  68
#define VSTR2  520
#define PSTR2  132
#define QB_F   (64 * QSTR2)           /* 4352 floats per Q buf  */
#define KB_F   (128 * KSTR2)          /* 8704 floats per K buf  */
#define VB_F   (16 * VSTR2)           /* 8320 floats per V buf  */
#define OFF_Q  0
#define OFF_K  (2 * QB_F)             /* 8704  */
#define OFF_V  (OFF_K + 2 * KB_F)     /* 26112 */
#define OFF_P  (OFF_V + 2 * VB_F)     /* 42752 */
#define OFF_L  (OFF_P + 64 * PSTR2)   /* 51200 */
#define ATTN_SMEM ((OFF_L + 256 + 16) * 4)

__global__ __launch_bounds__(512, 1) void attn_mma_kernel(float* __restrict__ Out)
{
    extern __shared__ __align__(16) float sm[];
    const int tid = threadIdx.x, lane = tid & 31, warp = tid >> 5;
    const int mg = warp & 3, hq = warp >> 2;
    const int g = lane >> 2, t = lane & 3;
    const int qt = blockIdx.x, b = blockIdx.y;

    const float* Qg = g_Q + ((size_t)b * SS + qt * 64) * DD;
    const float* Kb = g_K + (size_t)b * SS * DD;
    const float* Vb = g_V + (size_t)b * SS * DD;

    // per-thread cp.async coordinates
    const int qi = tid, qr = qi >> 4, qc = (qi & 15) * 4;         // Q: 2 iters j*512
    const int ki = tid, kr = ki >> 4, kc = (ki & 15) * 4;         // K: 4 iters
    const int vi = tid, vr = vi >> 7, vc4 = (vi & 127) * 4;       // V: 4 iters

    // --- issue helpers (each thread's share of one chunk) ---
    auto issue_qk = [&](int c, int buf, const float* Kt) {
        uint32_t qdst = smem_u32(&sm[OFF_Q + buf * QB_F]);
        uint32_t kdst = smem_u32(&sm[OFF_K + buf * KB_F]);
#pragma unroll
        for (int j = 0; j < 2; j++) {
            int r = qr + j * 32;
            CP_ASYNC16(qdst + (uint32_t)(r * QSTR2 + qc) * 4,
                       &Qg[(size_t)r * DD + c * 64 + qc]);
        }
#pragma unroll
        for (int j = 0; j < 4; j++) {
            int r = kr + j * 32;
            CP_ASYNC16(kdst + (uint32_t)(r * KSTR2 + kc) * 4,
                       &Kt[(size_t)r * DD + c * 64 + kc]);
        }
        CP_COMMIT();
    };
    auto issue_v = [&](int v, const float* Vt) {
        uint32_t vdst = smem_u32(&sm[OFF_V + (v & 1) * VB_F]);
#pragma unroll
        for (int j = 0; j < 4; j++) {
            int r = vr + j * 4;
            CP_ASYNC16(vdst + (uint32_t)(r * VSTR2 + vc4) * 4,
                       &Vt[(size_t)(v * 16 + r) * DD + vc4]);
        }
        CP_COMMIT();
    };

    float oacc[16][4];
#pragma unroll
    for (int nb = 0; nb < 16; nb++)
#pragma unroll
        for (int j = 0; j < 4; j++) oacc[nb][j] = 0.f;

    float lsum0 = 0.f, lsum1 = 0.f;
    const float C1 = 0.06375871651397899f;  // log2(e)/sqrt(512)
    const int rowA = 16 * mg + g;

    issue_qk(0, 0, Kb + (size_t)0);  // tile 0, chunk 0

    for (int kt = 0; kt < 32; kt++) {
        const float* Kt = Kb + (size_t)(kt * 128) * DD;
        const float* Vt = Vb + (size_t)(kt * 128) * DD;
        const float* KtN = Kb + (size_t)(((kt + 1) & 31) * 128) * DD;

        float sacc[4][4];
#pragma unroll
        for (int nb = 0; nb < 4; nb++)
#pragma unroll
            for (int j = 0; j < 4; j++) sacc[nb][j] = 0.f;

        // ---------------- GEMM1: S = Q.K^T, 8 chunks of 64 dims ----------------
        for (int c = 0; c < 8; c++) {
            if (c < 7) { issue_qk(c + 1, (c + 1) & 1, Kt); CP_WAIT(1); }
            else       { CP_WAIT(0); }
            __syncthreads();
            const float* qp = &sm[OFF_Q + (c & 1) * QB_F + rowA * QSTR2];
            const float* kp = &sm[OFF_K + (c & 1) * KB_F + (hq * 32 + g) * KSTR2];
#pragma unroll
            for (int ks = 0; ks < 8; ks++) {
                uint32_t a0 = __float_as_uint(qp[ks * 8 + t]);
                uint32_t a1 = __float_as_uint(qp[8 * QSTR2 + ks * 8 + t]);
                uint32_t a2 = __float_as_uint(qp[ks * 8 + t + 4]);
                uint32_t a3 = __float_as_uint(qp[8 * QSTR2 + ks * 8 + t + 4]);
#pragma unroll
                for (int nb = 0; nb < 4; nb++) {
                    uint32_t b0 = __float_as_uint(kp[nb * 8 * KSTR2 + ks * 8 + t]);
                    uint32_t b1 = __float_as_uint(kp[nb * 8 * KSTR2 + ks * 8 + t + 4]);
                    mma8(sacc[nb], a0, a1, a2, a3, b0, b1);
                }
            }
            __syncthreads();
        }

        // prefetch next tile's QK chunk 0 (buf0 free) + first two V chunks
        issue_qk(0, 0, KtN);
        issue_v(0, Vt);
        issue_v(1, Vt);

        // ---------------- softmax: p = exp2(s*C1); P -> smem ----------------
        {
            float* pr = &sm[OFF_P + rowA * PSTR2 + hq * 32 + 2 * t];
#pragma unroll
            for (int nb = 0; nb < 4; nb++) {
                float p0 = ex2(sacc[nb][0] * C1), p1 = ex2(sacc[nb][1] * C1);
                float p2 = ex2(sacc[nb][2] * C1), p3 = ex2(sacc[nb][3] * C1);
                lsum0 += p0 + p1; lsum1 += p2 + p3;
                *(float2*)&pr[nb * 8] = make_float2(tf32r(p0), tf32r(p1));
                *(float2*)&pr[8 * PSTR2 + nb * 8] = make_float2(tf32r(p2), tf32r(p3));
            }
        }
        __syncthreads();   // P visible before GEMM2 reads

        // ---------------- GEMM2: O += P.V, 8 key-chunks of 16 ----------------
        for (int v = 0; v < 8; v++) {
            if (v < 7) CP_WAIT(1); else CP_WAIT(0);
            __syncthreads();
            const float* pp = &sm[OFF_P + rowA * PSTR2 + v * 16];
            const float* vp = &sm[OFF_V + (v & 1) * VB_F];
#pragma unroll
            for (int ks = 0; ks < 2; ks++) {
                uint32_t a0 = __float_as_uint(pp[ks * 8 + t]);
                uint32_t a1 = __float_as_uint(pp[8 * PSTR2 + ks * 8 + t]);
                uint32_t a2 = __float_as_uint(pp[ks * 8 + t + 4]);
                uint32_t a3 = __float_as_uint(pp[8 * PSTR2 + ks * 8 + t + 4]);
                const float* vrow = &vp[(ks * 8 + t) * VSTR2 + hq * 128 + g];
#pragma unroll
                for (int nb = 0; nb < 16; nb++) {
                    uint32_t b0 = __float_as_uint(vrow[nb * 8]);
                    uint32_t b1 = __float_as_uint(vrow[4 * VSTR2 + nb * 8]);
                    mma8(oacc[nb], a0, a1, a2, a3, b0, b1);
                }
            }
            __syncthreads();
            if (v < 6) issue_v(v + 2, Vt);
        }
    }

    // ---- row-sum reduce: t lanes via shuffle, hq warps via smem ----
    lsum0 += __shfl_xor_sync(~0u, lsum0, 1); lsum0 += __shfl_xor_sync(~0u, lsum0, 2);
    lsum1 += __shfl_xor_sync(~0u, lsum1, 1); lsum1 += __shfl_xor_sync(~0u, lsum1, 2);
    if (t == 0) {
        sm[OFF_L + rowA * 4 + hq] = lsum0;
        sm[OFF_L + (rowA + 8) * 4 + hq] = lsum1;
    }
    __syncthreads();
    const float inv0 = 1.f / (sm[OFF_L + rowA * 4 + 0] + sm[OFF_L + rowA * 4 + 1] +
                              sm[OFF_L + rowA * 4 + 2] + sm[OFF_L + rowA * 4 + 3]);
    const float inv1 = 1.f / (sm[OFF_L + (rowA + 8) * 4 + 0] + sm[OFF_L + (rowA + 8) * 4 + 1] +
                              sm[OFF_L + (rowA + 8) * 4 + 2] + sm[OFF_L + (rowA + 8) * 4 + 3]);

    float* Og = Out + ((size_t)b * SS + qt * 64) * DD;
#pragma unroll
    for (int nb = 0; nb < 16; nb++) {
        int dcol = hq * 128 + nb * 8 + 2 * t;
        *(float2*)&Og[(size_t)rowA * DD + dcol] =
            make_float2(oacc[nb][0] * inv0, oacc[nb][1] * inv0);
        *(float2*)&Og[(size_t)(rowA + 8) * DD + dcol] =
            make_float2(oacc[nb][2] * inv1, oacc[nb][3] * inv1);
    }
}

// ===========================================================================
extern "C" void kernel_launch(void* const* d_in, const int* in_sizes, int n_in,
                              void* d_out, int out_size)
{
    const float* X  = (const float*)d_in[0];
    const float* Wq = (const float*)d_in[1];
    const float* bq = (const float*)d_in[2];
    const float* Wk = (const float*)d_in[3];
    const float* bk = (const float*)d_in[4];
    const float* Wv = (const float*)d_in[5];
    const float* bv = (const float*)d_in[6];
    float* Out = (float*)d_out;

    cudaFuncSetAttribute(qkv_mma_kernel,
                         cudaFuncAttributeMaxDynamicSharedMemorySize, PJ_SMEM);
    cudaFuncSetAttribute(attn_mma_kernel,
                         cudaFuncAttributeMaxDynamicSharedMemorySize, ATTN_SMEM);

    dim3 gp(DD / 128, (BB * SS) / 128, 3);
    qkv_mma_kernel<<<gp, 256, PJ_SMEM>>>(X, Wq, bq, Wk, bk, Wv, bv);

    dim3 ga(SS / 64, BB);
    attn_mma_kernel<<<ga, 512, ATTN_SMEM>>>(Out);
}

// round 16
// speedup vs baseline: 10.3025x; 1.2629x over previous
#include <cuda_runtime.h>
#include <cuda_bf16.h>
#include <cstdint>
#include <math.h>
#include <string.h>

#define BB 4
#define SS 4096
#define DD 512

__device__ float g_Q[BB * SS * DD];
__device__ float g_K[BB * SS * DD];
// V stored bf16, key-pair interleaved: element (s,d) at (s&~1)*DD + d*2 + (s&1)
__device__ __nv_bfloat16 g_Vh[BB * SS * DD];

__device__ __forceinline__ float tf32r(float x) {
    float y; asm("cvt.rna.tf32.f32 %0, %1;" : "=f"(y) : "f"(x)); return y;
}
__device__ __forceinline__ float4 tf32r4(float4 v) {
    v.x = tf32r(v.x); v.y = tf32r(v.y); v.z = tf32r(v.z); v.w = tf32r(v.w);
    return v;
}
__device__ __forceinline__ float ex2(float x) {
    float y; asm("ex2.approx.ftz.f32 %0, %1;" : "=f"(y) : "f"(x)); return y;
}
__device__ __forceinline__ void mma8(float* d, uint32_t a0, uint32_t a1,
                                     uint32_t a2, uint32_t a3,
                                     uint32_t b0, uint32_t b1) {
    asm volatile(
        "mma.sync.aligned.m16n8k8.row.col.f32.tf32.tf32.f32 "
        "{%0,%1,%2,%3}, {%4,%5,%6,%7}, {%8,%9}, {%0,%1,%2,%3};"
        : "+f"(d[0]), "+f"(d[1]), "+f"(d[2]), "+f"(d[3])
        : "r"(a0), "r"(a1), "r"(a2), "r"(a3), "r"(b0), "r"(b1));
}
__device__ __forceinline__ void mma16bf(float* d, uint32_t a0, uint32_t a1,
                                        uint32_t a2, uint32_t a3,
                                        uint32_t b0, uint32_t b1) {
    asm volatile(
        "mma.sync.aligned.m16n8k16.row.col.f32.bf16.bf16.f32 "
        "{%0,%1,%2,%3}, {%4,%5,%6,%7}, {%8,%9}, {%0,%1,%2,%3};"
        : "+f"(d[0]), "+f"(d[1]), "+f"(d[2]), "+f"(d[3])
        : "r"(a0), "r"(a1), "r"(a2), "r"(a3), "r"(b0), "r"(b1));
}
__device__ __forceinline__ uint32_t smem_u32(const void* p) {
    return (uint32_t)__cvta_generic_to_shared(p);
}
__device__ __forceinline__ uint32_t pack_bf2(float lo, float hi) {
    __nv_bfloat162 h = __floats2bfloat162_rn(lo, hi);
    uint32_t u; memcpy(&u, &h, 4); return u;
}
#define CP_ASYNC16(dst_u32, src_ptr) \
    asm volatile("cp.async.cg.shared.global [%0], [%1], 16;" \
                 :: "r"(dst_u32), "l"(src_ptr))
#define CP_COMMIT() asm volatile("cp.async.commit_group;" ::: "memory")
#define CP_WAIT(N)  asm volatile("cp.async.wait_group %0;" :: "n"(N) : "memory")

// ===========================================================================
// Kernel 1: QKV projection via mma.sync tf32.  Q/K written fp32 (tf32-rna);
// V written bf16 key-pair-interleaved into g_Vh.
// ===========================================================================
#define PJ_STR 68
#define PJ_SMEM (34816 * 4)

__global__ __launch_bounds__(256, 1) void qkv_mma_kernel(
    const float* __restrict__ X,
    const float* __restrict__ Wq, const float* __restrict__ bq,
    const float* __restrict__ Wk, const float* __restrict__ bk,
    const float* __restrict__ Wv, const float* __restrict__ bv)
{
    extern __shared__ __align__(16) float sm[];
    const int pz = blockIdx.z;
    const float* __restrict__ W    = (pz == 0) ? Wq : (pz == 1) ? Wk : Wv;
    const float* __restrict__ bias = (pz == 0) ? bq : (pz == 1) ? bk : bv;
    float* __restrict__ Y          = (pz == 0) ? g_Q : g_K;

    const int tid = threadIdx.x, lane = tid & 31, warp = tid >> 5;
    const int mg = warp & 3, nh = warp >> 2;
    const int g = lane >> 2, t = lane & 3;
    const int row0 = blockIdx.y * 128, col0 = blockIdx.x * 128;

    float4 pfx[8], pfw[8];
#pragma unroll
    for (int j = 0; j < 8; j++) {
        int i = tid + j * 256, r = i >> 4, c4 = i & 15;
        pfx[j] = __ldg((const float4*)&X[(size_t)(row0 + r) * DD + c4 * 4]);
        pfw[j] = __ldg((const float4*)&W[(size_t)(col0 + r) * DD + c4 * 4]);
    }

    float acc[2][8][4];
#pragma unroll
    for (int mt = 0; mt < 2; mt++)
#pragma unroll
        for (int nb = 0; nb < 8; nb++)
#pragma unroll
            for (int j = 0; j < 4; j++) acc[mt][nb][j] = 0.f;

    for (int c = 0; c < 8; c++) {
        float* Ab = sm + (c & 1) * 17408;
        float* Bb = Ab + 8704;
#pragma unroll
        for (int j = 0; j < 8; j++) {
            int i = tid + j * 256, r = i >> 4, c4 = i & 15;
            *(float4*)&Ab[r * PJ_STR + c4 * 4] = tf32r4(pfx[j]);
            *(float4*)&Bb[r * PJ_STR + c4 * 4] = tf32r4(pfw[j]);
        }
        if (c < 7) {
#pragma unroll
            for (int j = 0; j < 8; j++) {
                int i = tid + j * 256, r = i >> 4, c4 = i & 15;
                pfx[j] = __ldg((const float4*)&X[(size_t)(row0 + r) * DD + (c + 1) * 64 + c4 * 4]);
                pfw[j] = __ldg((const float4*)&W[(size_t)(col0 + r) * DD + (c + 1) * 64 + c4 * 4]);
            }
        }
        __syncthreads();
        const float* ap = &Ab[(32 * mg + g) * PJ_STR];
        const float* bp = &Bb[(64 * nh + g) * PJ_STR];
#pragma unroll
        for (int ks = 0; ks < 8; ks++) {
            uint32_t a00 = __float_as_uint(ap[ks * 8 + t]);
            uint32_t a01 = __float_as_uint(ap[8 * PJ_STR + ks * 8 + t]);
            uint32_t a02 = __float_as_uint(ap[ks * 8 + t + 4]);
            uint32_t a03 = __float_as_uint(ap[8 * PJ_STR + ks * 8 + t + 4]);
            uint32_t a10 = __float_as_uint(ap[16 * PJ_STR + ks * 8 + t]);
            uint32_t a11 = __float_as_uint(ap[24 * PJ_STR + ks * 8 + t]);
            uint32_t a12 = __float_as_uint(ap[16 * PJ_STR + ks * 8 + t + 4]);
            uint32_t a13 = __float_as_uint(ap[24 * PJ_STR + ks * 8 + t + 4]);
#pragma unroll
            for (int nb = 0; nb < 8; nb++) {
                uint32_t b0 = __float_as_uint(bp[nb * 8 * PJ_STR + ks * 8 + t]);
                uint32_t b1 = __float_as_uint(bp[nb * 8 * PJ_STR + ks * 8 + t + 4]);
                mma8(acc[0][nb], a00, a01, a02, a03, b0, b1);
                mma8(acc[1][nb], a10, a11, a12, a13, b0, b1);
            }
        }
        __syncthreads();
    }

#pragma unroll
    for (int mt = 0; mt < 2; mt++)
#pragma unroll
        for (int nb = 0; nb < 8; nb++) {
            int col = col0 + 64 * nh + 8 * nb + 2 * t;
            float b0v = __ldg(&bias[col]), b1v = __ldg(&bias[col + 1]);
            int r0 = row0 + 32 * mg + 16 * mt + g, r1 = r0 + 8;
            float v00 = acc[mt][nb][0] + b0v; v00 = v00 > 0.f ? v00 : 0.f;
            float v01 = acc[mt][nb][1] + b1v; v01 = v01 > 0.f ? v01 : 0.f;
            float v10 = acc[mt][nb][2] + b0v; v10 = v10 > 0.f ? v10 : 0.f;
            float v11 = acc[mt][nb][3] + b1v; v11 = v11 > 0.f ? v11 : 0.f;
            if (pz == 2) {
                size_t i0 = (size_t)(r0 & ~1) * DD + col * 2 + (r0 & 1);
                size_t i1 = (size_t)(r1 & ~1) * DD + col * 2 + (r1 & 1);
                g_Vh[i0]     = __float2bfloat16_rn(v00);
                g_Vh[i0 + 2] = __float2bfloat16_rn(v01);
                g_Vh[i1]     = __float2bfloat16_rn(v10);
                g_Vh[i1 + 2] = __float2bfloat16_rn(v11);
            } else {
                *(float2*)&Y[(size_t)r0 * DD + col] = make_float2(tf32r(v00), tf32r(v01));
                *(float2*)&Y[(size_t)r1 * DD + col] = make_float2(tf32r(v10), tf32r(v11));
            }
        }
}

// ===========================================================================
// Kernel 2: flash attention. GEMM1 tf32 (Q.K^T), GEMM2 bf16 m16n8k16 (P.V).
// 512 thr / 16 warps = (mg4, hq4). Key-tile 128. cp.async, single barrier
// per phase (issue-after-barrier); QK double-buffered, V triple-buffered.
// Word-unit smem offsets. All fragment strides bank-bijective.
// ===========================================================================
#define QSTR2  68                       /* floats */
#define KSTR2  68
#define PSTRW  68                       /* words = 136 bf16 per P row  */
#define VSTRW  520                      /* words per V key-pair row    */
#define QB_F   (64 * QSTR2)             /* 4352  */
#define KB_F   (128 * KSTR2)            /* 8704  */
#define VB_W   (8 * VSTRW)              /* 4160  */
#define OFF_Q  0
#define OFF_K  (2 * QB_F)               /* 8704  */
#define OFF_V  (OFF_K + 2 * KB_F)       /* 26112 */
#define OFF_P  (OFF_V + 3 * VB_W)       /* 38592 */
#define OFF_L  (OFF_P + 64 * PSTRW)     /* 42944 */
#define ATTN_SMEM ((OFF_L + 256 + 16) * 4)

__global__ __launch_bounds__(512, 1) void attn_mma_kernel(float* __restrict__ Out)
{
    extern __shared__ __align__(16) float sm[];
    uint32_t* pw = (uint32_t*)sm;
    const int tid = threadIdx.x, lane = tid & 31, warp = tid >> 5;
    const int mg = warp & 3, hq = warp >> 2;
    const int g = lane >> 2, t = lane & 3;
    const int qt = blockIdx.x, b = blockIdx.y;

    const float* Qg = g_Q + ((size_t)b * SS + qt * 64) * DD;
    const float* Kb = g_K + (size_t)b * SS * DD;
    const __nv_bfloat16* Vhb = g_Vh + (size_t)b * SS * DD;

    const int qr = tid >> 4, qc = (tid & 15) * 4;   // Q cp coords (2 iters)
    const int kr = tid >> 4, kc = (tid & 15) * 4;   // K cp coords (4 iters)
    const int vr2 = tid >> 6, vcw = (tid & 63) * 4; // V cp coords (2 iters)

    auto issue_qk = [&](int c, int buf, const float* Kt) {
        uint32_t qdst = smem_u32(&sm[OFF_Q + buf * QB_F]);
        uint32_t kdst = smem_u32(&sm[OFF_K + buf * KB_F]);
#pragma unroll
        for (int j = 0; j < 2; j++) {
            int r = qr + j * 32;
            CP_ASYNC16(qdst + (uint32_t)(r * QSTR2 + qc) * 4,
                       &Qg[(size_t)r * DD + c * 64 + qc]);
        }
#pragma unroll
        for (int j = 0; j < 4; j++) {
            int r = kr + j * 32;
            CP_ASYNC16(kdst + (uint32_t)(r * KSTR2 + kc) * 4,
                       &Kt[(size_t)r * DD + c * 64 + kc]);
        }
        CP_COMMIT();
    };
    auto issue_v = [&](int v, const __nv_bfloat16* Vth) {
        uint32_t vdst = smem_u32(&pw[OFF_V + (v % 3) * VB_W + vr2 * VSTRW + vcw]);
        const __nv_bfloat16* src = Vth + (size_t)(v * 8 + vr2) * 1024 + vcw * 2;
#pragma unroll
        for (int j = 0; j < 2; j++)
            CP_ASYNC16(vdst + (uint32_t)(j * 256) * 4, src + j * 512);
        CP_COMMIT();
    };

    float oacc[16][4];
#pragma unroll
    for (int nb = 0; nb < 16; nb++)
#pragma unroll
        for (int j = 0; j < 4; j++) oacc[nb][j] = 0.f;

    float lsum0 = 0.f, lsum1 = 0.f;
    const float C1 = 0.06375871651397899f;  // log2(e)/sqrt(512)
    const int rowA = 16 * mg + g;

    issue_qk(0, 0, Kb);   // tile 0 chunk 0

    for (int kt = 0; kt < 32; kt++) {
        const float* Kt = Kb + (size_t)(kt * 128) * DD;
        const __nv_bfloat16* Vth = Vhb + (size_t)(kt * 128) * DD;
        const float* KtN = Kb + (size_t)(((kt + 1) & 31) * 128) * DD;

        float sacc[4][4];
#pragma unroll
        for (int nb = 0; nb < 4; nb++)
#pragma unroll
            for (int j = 0; j < 4; j++) sacc[nb][j] = 0.f;

        // ------- GEMM1: S = Q.K^T, 8 chunks of 64 dims, 1 barrier/phase -------
        for (int c = 0; c < 8; c++) {
            CP_WAIT(0);
            __syncthreads();
            if (c < 7) issue_qk(c + 1, (c + 1) & 1, Kt);
            else       { issue_v(0, Vth); issue_v(1, Vth); }
            const float* qp = &sm[OFF_Q + (c & 1) * QB_F + rowA * QSTR2];
            const float* kp = &sm[OFF_K + (c & 1) * KB_F + (hq * 32 + g) * KSTR2];
#pragma unroll
            for (int ks = 0; ks < 8; ks++) {
                uint32_t a0 = __float_as_uint(qp[ks * 8 + t]);
                uint32_t a1 = __float_as_uint(qp[8 * QSTR2 + ks * 8 + t]);
                uint32_t a2 = __float_as_uint(qp[ks * 8 + t + 4]);
                uint32_t a3 = __float_as_uint(qp[8 * QSTR2 + ks * 8 + t + 4]);
#pragma unroll
                for (int nb = 0; nb < 4; nb++) {
                    uint32_t b0 = __float_as_uint(kp[nb * 8 * KSTR2 + ks * 8 + t]);
                    uint32_t b1 = __float_as_uint(kp[nb * 8 * KSTR2 + ks * 8 + t + 4]);
                    mma8(sacc[nb], a0, a1, a2, a3, b0, b1);
                }
            }
        }

        // ------- softmax: p = exp2(s*C1); P -> smem as packed bf16 -------
#pragma unroll
        for (int nb = 0; nb < 4; nb++) {
            float p0 = ex2(sacc[nb][0] * C1), p1 = ex2(sacc[nb][1] * C1);
            float p2 = ex2(sacc[nb][2] * C1), p3 = ex2(sacc[nb][3] * C1);
            lsum0 += p0 + p1; lsum1 += p2 + p3;
            pw[OFF_P + rowA * PSTRW + hq * 16 + nb * 4 + t]       = pack_bf2(p0, p1);
            pw[OFF_P + (rowA + 8) * PSTRW + hq * 16 + nb * 4 + t] = pack_bf2(p2, p3);
        }

        // ------- GEMM2: O += P.V, 8 phases of 16 keys, bf16 k16 -------
#pragma unroll
        for (int v = 0; v < 8; v++) {
            if (v == 6) { CP_WAIT(2); } else { CP_WAIT(1); }
            __syncthreads();
            if (v < 5)       issue_v(v + 2, Vth);
            else if (v == 5) { issue_v(7, Vth); issue_qk(0, 0, KtN); }
            uint32_t a0 = pw[OFF_P + rowA * PSTRW + v * 8 + t];
            uint32_t a1 = pw[OFF_P + (rowA + 8) * PSTRW + v * 8 + t];
            uint32_t a2 = pw[OFF_P + rowA * PSTRW + v * 8 + t + 4];
            uint32_t a3 = pw[OFF_P + (rowA + 8) * PSTRW + v * 8 + t + 4];
            const uint32_t* vw = &pw[OFF_V + (v % 3) * VB_W];
#pragma unroll
            for (int nb = 0; nb < 16; nb++) {
                uint32_t b0 = vw[t * VSTRW + hq * 128 + nb * 8 + g];
                uint32_t b1 = vw[(t + 4) * VSTRW + hq * 128 + nb * 8 + g];
                mma16bf(oacc[nb], a0, a1, a2, a3, b0, b1);
            }
        }
    }

    // ---- row-sum reduce: t lanes via shuffle, hq warps via smem ----
    lsum0 += __shfl_xor_sync(~0u, lsum0, 1); lsum0 += __shfl_xor_sync(~0u, lsum0, 2);
    lsum1 += __shfl_xor_sync(~0u, lsum1, 1); lsum1 += __shfl_xor_sync(~0u, lsum1, 2);
    if (t == 0) {
        sm[OFF_L + rowA * 4 + hq] = lsum0;
        sm[OFF_L + (rowA + 8) * 4 + hq] = lsum1;
    }
    __syncthreads();
    const float inv0 = 1.f / (sm[OFF_L + rowA * 4 + 0] + sm[OFF_L + rowA * 4 + 1] +
                              sm[OFF_L + rowA * 4 + 2] + sm[OFF_L + rowA * 4 + 3]);
    const float inv1 = 1.f / (sm[OFF_L + (rowA + 8) * 4 + 0] + sm[OFF_L + (rowA + 8) * 4 + 1] +
                              sm[OFF_L + (rowA + 8) * 4 + 2] + sm[OFF_L + (rowA + 8) * 4 + 3]);

    float* Og = Out + ((size_t)b * SS + qt * 64) * DD;
#pragma unroll
    for (int nb = 0; nb < 16; nb++) {
        int dcol = hq * 128 + nb * 8 + 2 * t;
        *(float2*)&Og[(size_t)rowA * DD + dcol] =
            make_float2(oacc[nb][0] * inv0, oacc[nb][1] * inv0);
        *(float2*)&Og[(size_t)(rowA + 8) * DD + dcol] =
            make_float2(oacc[nb][2] * inv1, oacc[nb][3] * inv1);
    }
}

// ===========================================================================
extern "C" void kernel_launch(void* const* d_in, const int* in_sizes, int n_in,
                              void* d_out, int out_size)
{
    const float* X  = (const float*)d_in[0];
    const float* Wq = (const float*)d_in[1];
    const float* bq = (const float*)d_in[2];
    const float* Wk = (const float*)d_in[3];
    const float* bk = (const float*)d_in[4];
    const float* Wv = (const float*)d_in[5];
    const float* bv = (const float*)d_in[6];
    float* Out = (float*)d_out;

    cudaFuncSetAttribute(qkv_mma_kernel,
                         cudaFuncAttributeMaxDynamicSharedMemorySize, PJ_SMEM);
    cudaFuncSetAttribute(attn_mma_kernel,
                         cudaFuncAttributeMaxDynamicSharedMemorySize, ATTN_SMEM);

    dim3 gp(DD / 128, (BB * SS) / 128, 3);
    qkv_mma_kernel<<<gp, 256, PJ_SMEM>>>(X, Wq, bq, Wk, bk, Wv, bv);

    dim3 ga(SS / 64, BB);
    attn_mma_kernel<<<ga, 512, ATTN_SMEM>>>(Out);
}

// round 17
// speedup vs baseline: 11.1627x; 1.0835x over previous
#include <cuda_runtime.h>
#include <cuda_bf16.h>
#include <cstdint>
#include <math.h>
#include <string.h>

#define BB 4
#define SS 4096
#define DD 512

__device__ float g_Q[BB * SS * DD];
__device__ float g_K[BB * SS * DD];
// V stored bf16, key-pair interleaved: element (s,d) at (s&~1)*DD + d*2 + (s&1)
__device__ __nv_bfloat16 g_Vh[BB * SS * DD];

__device__ __forceinline__ float tf32r(float x) {
    float y; asm("cvt.rna.tf32.f32 %0, %1;" : "=f"(y) : "f"(x)); return y;
}
__device__ __forceinline__ float4 tf32r4(float4 v) {
    v.x = tf32r(v.x); v.y = tf32r(v.y); v.z = tf32r(v.z); v.w = tf32r(v.w);
    return v;
}
__device__ __forceinline__ float ex2(float x) {
    float y; asm("ex2.approx.ftz.f32 %0, %1;" : "=f"(y) : "f"(x)); return y;
}
__device__ __forceinline__ void mma8(float* d, uint32_t a0, uint32_t a1,
                                     uint32_t a2, uint32_t a3,
                                     uint32_t b0, uint32_t b1) {
    asm volatile(
        "mma.sync.aligned.m16n8k8.row.col.f32.tf32.tf32.f32 "
        "{%0,%1,%2,%3}, {%4,%5,%6,%7}, {%8,%9}, {%0,%1,%2,%3};"
        : "+f"(d[0]), "+f"(d[1]), "+f"(d[2]), "+f"(d[3])
        : "r"(a0), "r"(a1), "r"(a2), "r"(a3), "r"(b0), "r"(b1));
}
__device__ __forceinline__ void mma16bf(float* d, uint32_t a0, uint32_t a1,
                                        uint32_t a2, uint32_t a3,
                                        uint32_t b0, uint32_t b1) {
    asm volatile(
        "mma.sync.aligned.m16n8k16.row.col.f32.bf16.bf16.f32 "
        "{%0,%1,%2,%3}, {%4,%5,%6,%7}, {%8,%9}, {%0,%1,%2,%3};"
        : "+f"(d[0]), "+f"(d[1]), "+f"(d[2]), "+f"(d[3])
        : "r"(a0), "r"(a1), "r"(a2), "r"(a3), "r"(b0), "r"(b1));
}
__device__ __forceinline__ void ldsm4(uint32_t addr, uint32_t& r0, uint32_t& r1,
                                      uint32_t& r2, uint32_t& r3) {
    asm volatile("ldmatrix.sync.aligned.m8n8.x4.shared.b16 {%0,%1,%2,%3}, [%4];"
                 : "=r"(r0), "=r"(r1), "=r"(r2), "=r"(r3) : "r"(addr));
}
__device__ __forceinline__ uint32_t smem_u32(const void* p) {
    return (uint32_t)__cvta_generic_to_shared(p);
}
__device__ __forceinline__ uint32_t pack_bf2(float lo, float hi) {
    __nv_bfloat162 h = __floats2bfloat162_rn(lo, hi);
    uint32_t u; memcpy(&u, &h, 4); return u;
}
#define CP_ASYNC16(dst_u32, src_ptr) \
    asm volatile("cp.async.cg.shared.global [%0], [%1], 16;" \
                 :: "r"(dst_u32), "l"(src_ptr))
#define CP_COMMIT() asm volatile("cp.async.commit_group;" ::: "memory")
#define CP_WAIT(N)  asm volatile("cp.async.wait_group %0;" :: "n"(N) : "memory")

// ===========================================================================
// Kernel 1: QKV projection via mma.sync tf32 (unchanged from R16).
// ===========================================================================
#define PJ_STR 68
#define PJ_SMEM (34816 * 4)

__global__ __launch_bounds__(256, 1) void qkv_mma_kernel(
    const float* __restrict__ X,
    const float* __restrict__ Wq, const float* __restrict__ bq,
    const float* __restrict__ Wk, const float* __restrict__ bk,
    const float* __restrict__ Wv, const float* __restrict__ bv)
{
    extern __shared__ __align__(16) float sm[];
    const int pz = blockIdx.z;
    const float* __restrict__ W    = (pz == 0) ? Wq : (pz == 1) ? Wk : Wv;
    const float* __restrict__ bias = (pz == 0) ? bq : (pz == 1) ? bk : bv;
    float* __restrict__ Y          = (pz == 0) ? g_Q : g_K;

    const int tid = threadIdx.x, lane = tid & 31, warp = tid >> 5;
    const int mg = warp & 3, nh = warp >> 2;
    const int g = lane >> 2, t = lane & 3;
    const int row0 = blockIdx.y * 128, col0 = blockIdx.x * 128;

    float4 pfx[8], pfw[8];
#pragma unroll
    for (int j = 0; j < 8; j++) {
        int i = tid + j * 256, r = i >> 4, c4 = i & 15;
        pfx[j] = __ldg((const float4*)&X[(size_t)(row0 + r) * DD + c4 * 4]);
        pfw[j] = __ldg((const float4*)&W[(size_t)(col0 + r) * DD + c4 * 4]);
    }

    float acc[2][8][4];
#pragma unroll
    for (int mt = 0; mt < 2; mt++)
#pragma unroll
        for (int nb = 0; nb < 8; nb++)
#pragma unroll
            for (int j = 0; j < 4; j++) acc[mt][nb][j] = 0.f;

    for (int c = 0; c < 8; c++) {
        float* Ab = sm + (c & 1) * 17408;
        float* Bb = Ab + 8704;
#pragma unroll
        for (int j = 0; j < 8; j++) {
            int i = tid + j * 256, r = i >> 4, c4 = i & 15;
            *(float4*)&Ab[r * PJ_STR + c4 * 4] = tf32r4(pfx[j]);
            *(float4*)&Bb[r * PJ_STR + c4 * 4] = tf32r4(pfw[j]);
        }
        if (c < 7) {
#pragma unroll
            for (int j = 0; j < 8; j++) {
                int i = tid + j * 256, r = i >> 4, c4 = i & 15;
                pfx[j] = __ldg((const float4*)&X[(size_t)(row0 + r) * DD + (c + 1) * 64 + c4 * 4]);
                pfw[j] = __ldg((const float4*)&W[(size_t)(col0 + r) * DD + (c + 1) * 64 + c4 * 4]);
            }
        }
        __syncthreads();
        const float* ap = &Ab[(32 * mg + g) * PJ_STR];
        const float* bp = &Bb[(64 * nh + g) * PJ_STR];
#pragma unroll
        for (int ks = 0; ks < 8; ks++) {
            uint32_t a00 = __float_as_uint(ap[ks * 8 + t]);
            uint32_t a01 = __float_as_uint(ap[8 * PJ_STR + ks * 8 + t]);
            uint32_t a02 = __float_as_uint(ap[ks * 8 + t + 4]);
            uint32_t a03 = __float_as_uint(ap[8 * PJ_STR + ks * 8 + t + 4]);
            uint32_t a10 = __float_as_uint(ap[16 * PJ_STR + ks * 8 + t]);
            uint32_t a11 = __float_as_uint(ap[24 * PJ_STR + ks * 8 + t]);
            uint32_t a12 = __float_as_uint(ap[16 * PJ_STR + ks * 8 + t + 4]);
            uint32_t a13 = __float_as_uint(ap[24 * PJ_STR + ks * 8 + t + 4]);
#pragma unroll
            for (int nb = 0; nb < 8; nb++) {
                uint32_t b0 = __float_as_uint(bp[nb * 8 * PJ_STR + ks * 8 + t]);
                uint32_t b1 = __float_as_uint(bp[nb * 8 * PJ_STR + ks * 8 + t + 4]);
                mma8(acc[0][nb], a00, a01, a02, a03, b0, b1);
                mma8(acc[1][nb], a10, a11, a12, a13, b0, b1);
            }
        }
        __syncthreads();
    }

#pragma unroll
    for (int mt = 0; mt < 2; mt++)
#pragma unroll
        for (int nb = 0; nb < 8; nb++) {
            int col = col0 + 64 * nh + 8 * nb + 2 * t;
            float b0v = __ldg(&bias[col]), b1v = __ldg(&bias[col + 1]);
            int r0 = row0 + 32 * mg + 16 * mt + g, r1 = r0 + 8;
            float v00 = acc[mt][nb][0] + b0v; v00 = v00 > 0.f ? v00 : 0.f;
            float v01 = acc[mt][nb][1] + b1v; v01 = v01 > 0.f ? v01 : 0.f;
            float v10 = acc[mt][nb][2] + b0v; v10 = v10 > 0.f ? v10 : 0.f;
            float v11 = acc[mt][nb][3] + b1v; v11 = v11 > 0.f ? v11 : 0.f;
            if (pz == 2) {
                size_t i0 = (size_t)(r0 & ~1) * DD + col * 2 + (r0 & 1);
                size_t i1 = (size_t)(r1 & ~1) * DD + col * 2 + (r1 & 1);
                g_Vh[i0]     = __float2bfloat16_rn(v00);
                g_Vh[i0 + 2] = __float2bfloat16_rn(v01);
                g_Vh[i1]     = __float2bfloat16_rn(v10);
                g_Vh[i1 + 2] = __float2bfloat16_rn(v11);
            } else {
                *(float2*)&Y[(size_t)r0 * DD + col] = make_float2(tf32r(v00), tf32r(v01));
                *(float2*)&Y[(size_t)r1 * DD + col] = make_float2(tf32r(v10), tf32r(v11));
            }
        }
}

// ===========================================================================
// Kernel 2: flash attention. GEMM1 tf32 + ldmatrix frags; GEMM2 bf16 k16,
// P frags via ldmatrix, V scalar. 512 thr / 16 warps = (mg4, hq4).
// Key-tile 128; cp.async with single barrier per phase; QK db, V triple-buf.
// ===========================================================================
#define QSTR2  68                       /* floats */
#define KSTR2  68
#define PSTRW  68                       /* words = 136 bf16 per P row  */
#define VSTRW  520                      /* words per V key-pair row    */
#define QB_F   (64 * QSTR2)             /* 4352  */
#define KB_F   (128 * KSTR2)            /* 8704  */
#define VB_W   (8 * VSTRW)              /* 4160  */
#define OFF_Q  0
#define OFF_K  (2 * QB_F)               /* 8704  */
#define OFF_V  (OFF_K + 2 * KB_F)       /* 26112 */
#define OFF_P  (OFF_V + 3 * VB_W)       /* 38592 */
#define OFF_L  (OFF_P + 64 * PSTRW)     /* 42944 */
#define ATTN_SMEM ((OFF_L + 256 + 16) * 4)

__global__ __launch_bounds__(512, 1) void attn_mma_kernel(float* __restrict__ Out)
{
    extern __shared__ __align__(16) float sm[];
    uint32_t* pw = (uint32_t*)sm;
    const int tid = threadIdx.x, lane = tid & 31, warp = tid >> 5;
    const int mg = warp & 3, hq = warp >> 2;
    const int g = lane >> 2, t = lane & 3;
    const int mrow = lane & 7, mid = lane >> 3;   // ldmatrix row / matrix id
    const int qt = blockIdx.x, b = blockIdx.y;

    const float* Qg = g_Q + ((size_t)b * SS + qt * 64) * DD;
    const float* Kb = g_K + (size_t)b * SS * DD;
    const __nv_bfloat16* Vhb = g_Vh + (size_t)b * SS * DD;

    const int qr = tid >> 4, qc = (tid & 15) * 4;
    const int kr = tid >> 4, kc = (tid & 15) * 4;
    const int vr2 = tid >> 6, vcw = (tid & 63) * 4;

    auto issue_qk = [&](int c, int buf, const float* Kt) {
        uint32_t qdst = smem_u32(&sm[OFF_Q + buf * QB_F]);
        uint32_t kdst = smem_u32(&sm[OFF_K + buf * KB_F]);
#pragma unroll
        for (int j = 0; j < 2; j++) {
            int r = qr + j * 32;
            CP_ASYNC16(qdst + (uint32_t)(r * QSTR2 + qc) * 4,
                       &Qg[(size_t)r * DD + c * 64 + qc]);
        }
#pragma unroll
        for (int j = 0; j < 4; j++) {
            int r = kr + j * 32;
            CP_ASYNC16(kdst + (uint32_t)(r * KSTR2 + kc) * 4,
                       &Kt[(size_t)r * DD + c * 64 + kc]);
        }
        CP_COMMIT();
    };
    auto issue_v = [&](int v, const __nv_bfloat16* Vth) {
        uint32_t vdst = smem_u32(&pw[OFF_V + (v % 3) * VB_W + vr2 * VSTRW + vcw]);
        const __nv_bfloat16* src = Vth + (size_t)(v * 8 + vr2) * 1024 + vcw * 2;
#pragma unroll
        for (int j = 0; j < 2; j++)
            CP_ASYNC16(vdst + (uint32_t)(j * 256) * 4, src + j * 512);
        CP_COMMIT();
    };

    // ldmatrix lane-address components
    // A (Q, tf32): matrices = (row-half mid&1) x (k-half mid>>1) of 16x8 tile
    const int aQrow = 16 * mg + (mid & 1) * 8 + mrow;
    const int aQoff = (mid >> 1) * 4;
    // B (K, tf32): r0..r3 = {b0,b1} of nb and nb+1 : rows (mid>>1)*8, k-off (mid&1)*4
    const int bKrow = (mid >> 1) * 8 + mrow;
    const int bKoff = (mid & 1) * 4;
    // A (P, bf16 k16): same geometry as Q but word units
    const uint32_t aPbase =
        smem_u32(&pw[OFF_P + ((16 * mg + (mid & 1) * 8 + mrow)) * PSTRW + (mid >> 1) * 4]);

    float oacc[16][4];
#pragma unroll
    for (int nb = 0; nb < 16; nb++)
#pragma unroll
        for (int j = 0; j < 4; j++) oacc[nb][j] = 0.f;

    float lsum0 = 0.f, lsum1 = 0.f;
    const float C1 = 0.06375871651397899f;  // log2(e)/sqrt(512)
    const int rowA = 16 * mg + g;

    issue_qk(0, 0, Kb);   // tile 0 chunk 0

    for (int kt = 0; kt < 32; kt++) {
        const float* Kt = Kb + (size_t)(kt * 128) * DD;
        const __nv_bfloat16* Vth = Vhb + (size_t)(kt * 128) * DD;
        const float* KtN = Kb + (size_t)(((kt + 1) & 31) * 128) * DD;

        float sacc[4][4];
#pragma unroll
        for (int nb = 0; nb < 4; nb++)
#pragma unroll
            for (int j = 0; j < 4; j++) sacc[nb][j] = 0.f;

        // ------- GEMM1: S = Q.K^T, 8 chunks of 64 dims, ldmatrix frags -------
        for (int c = 0; c < 8; c++) {
            CP_WAIT(0);
            __syncthreads();
            if (c < 7) issue_qk(c + 1, (c + 1) & 1, Kt);
            else       { issue_v(0, Vth); issue_v(1, Vth); }
            const uint32_t aA =
                smem_u32(&sm[OFF_Q + (c & 1) * QB_F + aQrow * QSTR2 + aQoff]);
            const uint32_t aB0 =
                smem_u32(&sm[OFF_K + (c & 1) * KB_F + (hq * 32 + bKrow) * KSTR2 + bKoff]);
            const uint32_t aB1 = aB0 + 16 * KSTR2 * 4;
#pragma unroll
            for (int ks = 0; ks < 8; ks++) {
                uint32_t a0, a1, a2, a3, b00, b01, b10, b11, b20, b21, b30, b31;
                ldsm4(aA + ks * 32, a0, a1, a2, a3);
                ldsm4(aB0 + ks * 32, b00, b01, b10, b11);
                ldsm4(aB1 + ks * 32, b20, b21, b30, b31);
                mma8(sacc[0], a0, a1, a2, a3, b00, b01);
                mma8(sacc[1], a0, a1, a2, a3, b10, b11);
                mma8(sacc[2], a0, a1, a2, a3, b20, b21);
                mma8(sacc[3], a0, a1, a2, a3, b30, b31);
            }
        }

        // ------- softmax: p = exp2(s*C1); P -> smem as packed bf16 -------
#pragma unroll
        for (int nb = 0; nb < 4; nb++) {
            float p0 = ex2(sacc[nb][0] * C1), p1 = ex2(sacc[nb][1] * C1);
            float p2 = ex2(sacc[nb][2] * C1), p3 = ex2(sacc[nb][3] * C1);
            lsum0 += p0 + p1; lsum1 += p2 + p3;
            pw[OFF_P + rowA * PSTRW + hq * 16 + nb * 4 + t]       = pack_bf2(p0, p1);
            pw[OFF_P + (rowA + 8) * PSTRW + hq * 16 + nb * 4 + t] = pack_bf2(p2, p3);
        }

        // ------- GEMM2: O += P.V, 8 phases of 16 keys, bf16 k16 -------
#pragma unroll
        for (int v = 0; v < 8; v++) {
            if (v == 6) { CP_WAIT(2); } else { CP_WAIT(1); }
            __syncthreads();
            if (v < 5)       issue_v(v + 2, Vth);
            else if (v == 5) { issue_v(7, Vth); issue_qk(0, 0, KtN); }
            uint32_t a0, a1, a2, a3;
            ldsm4(aPbase + v * 32, a0, a1, a2, a3);
            const uint32_t* vw = &pw[OFF_V + (v % 3) * VB_W];
#pragma unroll
            for (int nb = 0; nb < 16; nb++) {
                uint32_t b0 = vw[t * VSTRW + hq * 128 + nb * 8 + g];
                uint32_t b1 = vw[(t + 4) * VSTRW + hq * 128 + nb * 8 + g];
                mma16bf(oacc[nb], a0, a1, a2, a3, b0, b1);
            }
        }
    }

    // ---- row-sum reduce: t lanes via shuffle, hq warps via smem ----
    lsum0 += __shfl_xor_sync(~0u, lsum0, 1); lsum0 += __shfl_xor_sync(~0u, lsum0, 2);
    lsum1 += __shfl_xor_sync(~0u, lsum1, 1); lsum1 += __shfl_xor_sync(~0u, lsum1, 2);
    if (t == 0) {
        sm[OFF_L + rowA * 4 + hq] = lsum0;
        sm[OFF_L + (rowA + 8) * 4 + hq] = lsum1;
    }
    __syncthreads();
    const float inv0 = 1.f / (sm[OFF_L + rowA * 4 + 0] + sm[OFF_L + rowA * 4 + 1] +
                              sm[OFF_L + rowA * 4 + 2] + sm[OFF_L + rowA * 4 + 3]);
    const float inv1 = 1.f / (sm[OFF_L + (rowA + 8) * 4 + 0] + sm[OFF_L + (rowA + 8) * 4 + 1] +
                              sm[OFF_L + (rowA + 8) * 4 + 2] + sm[OFF_L + (rowA + 8) * 4 + 3]);

    float* Og = Out + ((size_t)b * SS + qt * 64) * DD;
#pragma unroll
    for (int nb = 0; nb < 16; nb++) {
        int dcol = hq * 128 + nb * 8 + 2 * t;
        *(float2*)&Og[(size_t)rowA * DD + dcol] =
            make_float2(oacc[nb][0] * inv0, oacc[nb][1] * inv0);
        *(float2*)&Og[(size_t)(rowA + 8) * DD + dcol] =
            make_float2(oacc[nb][2] * inv1, oacc[nb][3] * inv1);
    }
}

// ===========================================================================
extern "C" void kernel_launch(void* const* d_in, const int* in_sizes, int n_in,
                              void* d_out, int out_size)
{
    const float* X  = (const float*)d_in[0];
    const float* Wq = (const float*)d_in[1];
    const float* bq = (const float*)d_in[2];
    const float* Wk = (const float*)d_in[3];
    const float* bk = (const float*)d_in[4];
    const float* Wv = (const float*)d_in[5];
    const float* bv = (const float*)d_in[6];
    float* Out = (float*)d_out;

    cudaFuncSetAttribute(qkv_mma_kernel,
                         cudaFuncAttributeMaxDynamicSharedMemorySize, PJ_SMEM);
    cudaFuncSetAttribute(attn_mma_kernel,
                         cudaFuncAttributeMaxDynamicSharedMemorySize, ATTN_SMEM);

    dim3 gp(DD / 128, (BB * SS) / 128, 3);
    qkv_mma_kernel<<<gp, 256, PJ_SMEM>>>(X, Wq, bq, Wk, bk, Wv, bv);

    dim3 ga(SS / 64, BB);
    attn_mma_kernel<<<ga, 512, ATTN_SMEM>>>(Out);
}